// round 1
// baseline (speedup 1.0000x reference)
#include <cuda_runtime.h>
#include <cuda_bf16.h>
#include <cstdint>

// ---------------------------------------------------------------------------
// DGCNN forward, restructured:
//   edge_conv(x) with feat=[nbr-ctr; ctr] ==
//     out[b,n,o] = lrelu( max_k ( u[b,idx[b,n,k],o] + t[b,n,o] ) )
//   where u = (s*W_a) @ x   (per-point GEMM, gathered by knn idx)
//         t = (s*(W_b-W_a)) @ x + (s*bias + bn_b)
//   (bn is affine with scale s = g/sqrt(1+eps); lrelu/max commute)
// This removes the K=20 factor from all edge-conv GEMMs.
// ---------------------------------------------------------------------------

#define B_   8
#define N_   1024
#define PTS  (B_ * N_)        // 8192
#define KNN  20
#define NEG_INF __int_as_float(0xff800000)

// scratch (static __device__ — no allocation allowed)
__device__ static float    g_xc[PTS * 512];        // concat feature buffer [8192][512]
__device__ static float    g_inner[PTS * 1024];    // inner products / conv5 output e
__device__ static float    g_u[PTS * 256];
__device__ static float    g_t[PTS * 256];
__device__ static float    g_xx[PTS];
__device__ static int      g_idx[PTS * KNN];
__device__ static float    g_w1s[256 * 128];
__device__ static float    g_wts[256 * 128];
__device__ static float    g_tb[256];
__device__ static unsigned g_pool[B_ * 1024];      // encoded-float max pool
__device__ static float    g_y1[B_ * 512];
__device__ static float    g_y2[B_ * 256];

// ---------------------------------------------------------------------------
// Generic fp32 GEMM: C[m,n] = sum_k A[m,k]*B[n,k] (+bias[n])
// A: M x K row-major (lda), B: N x K row-major (ldb). BM=128 BN=64 BK=16,
// 256 threads, 8x4 microtile.
// M % 128 == 0, N % 64 == 0 guaranteed by call sites; K arbitrary (guarded).
// ---------------------------------------------------------------------------
#define BM 128
#define BN 64
#define BK 16

__global__ void gemm_nt(const float* __restrict__ A, int lda, long long sA,
                        const float* __restrict__ B, int ldb, long long sB,
                        float* __restrict__ C, int ldc, long long sC,
                        int K, const float* __restrict__ bias)
{
    __shared__ float As[BK][BM + 4];
    __shared__ float Bs[BK][BN + 4];

    int bz = blockIdx.z;
    A += bz * sA; B += bz * sB; C += bz * sC;
    int m0 = blockIdx.y * BM;
    int n0 = blockIdx.x * BN;

    int tid = threadIdx.x;           // 256
    int tx = tid & 15;               // 0..15 -> n
    int ty = tid >> 4;               // 0..15 -> m
    int lk = tid & 15;               // loader k
    int lr = tid >> 4;               // loader row base

    float acc[8][4];
    #pragma unroll
    for (int i = 0; i < 8; i++)
        #pragma unroll
        for (int j = 0; j < 4; j++) acc[i][j] = 0.f;

    for (int k0 = 0; k0 < K; k0 += BK) {
        bool kin = (k0 + lk) < K;
        #pragma unroll
        for (int p = 0; p < 8; p++) {
            int r = lr + p * 16;
            As[lk][r] = kin ? A[(size_t)(m0 + r) * lda + k0 + lk] : 0.f;
        }
        #pragma unroll
        for (int p = 0; p < 4; p++) {
            int r = lr + p * 16;
            Bs[lk][r] = kin ? B[(size_t)(n0 + r) * ldb + k0 + lk] : 0.f;
        }
        __syncthreads();

        #pragma unroll
        for (int k = 0; k < BK; k++) {
            float4 a0 = *reinterpret_cast<const float4*>(&As[k][ty * 8]);
            float4 a1 = *reinterpret_cast<const float4*>(&As[k][ty * 8 + 4]);
            float4 b0 = *reinterpret_cast<const float4*>(&Bs[k][tx * 4]);
            float av[8] = {a0.x, a0.y, a0.z, a0.w, a1.x, a1.y, a1.z, a1.w};
            float bv[4] = {b0.x, b0.y, b0.z, b0.w};
            #pragma unroll
            for (int i = 0; i < 8; i++)
                #pragma unroll
                for (int j = 0; j < 4; j++)
                    acc[i][j] += av[i] * bv[j];
        }
        __syncthreads();
    }

    #pragma unroll
    for (int i = 0; i < 8; i++) {
        int m = m0 + ty * 8 + i;
        #pragma unroll
        for (int j = 0; j < 4; j++) {
            int n = n0 + tx * 4 + j;
            float v = acc[i][j];
            if (bias) v += bias[n];
            C[(size_t)m * ldc + n] = v;
        }
    }
}

// ---------------------------------------------------------------------------
// squared norms per point
// ---------------------------------------------------------------------------
__global__ void xx_kernel(const float* __restrict__ X, int lda, int C, float* __restrict__ xx)
{
    int p = blockIdx.x * 8 + (threadIdx.x >> 5);
    int lane = threadIdx.x & 31;
    const float* r = X + (size_t)p * lda;
    float s = 0.f;
    for (int c = lane; c < C; c += 32) { float v = r[c]; s += v * v; }
    #pragma unroll
    for (int off = 16; off; off >>= 1) s += __shfl_xor_sync(0xffffffffu, s, off);
    if (lane == 0) xx[p] = s;
}

// ---------------------------------------------------------------------------
// top-20 neighbors per row. warp per (b,n). key = 2*inner - xx[m]
// (constant -xx[n] dropped; self point is always top-1, matching reference).
// ---------------------------------------------------------------------------
__global__ void topk_kernel(const float* __restrict__ inner, const float* __restrict__ xx,
                            int* __restrict__ idx_out)
{
    __shared__ float skey[8][N_];
    int wid  = threadIdx.x >> 5;
    int lane = threadIdx.x & 31;
    int row  = blockIdx.x * 8 + wid;            // b*1024+n
    int b    = row >> 10;
    float* key = skey[wid];
    const float* r = inner + (size_t)row * N_;
    const float* xb = xx + b * N_;

    float lv = NEG_INF; int lm = -1;
    #pragma unroll
    for (int i = 0; i < 32; i++) {
        int m = i * 32 + lane;
        float v = 2.f * r[m] - xb[m];
        key[m] = v;
        if (v > lv) { lv = v; lm = m; }
    }
    __syncwarp();

    for (int it = 0; it < KNN; it++) {
        float v = lv; int m = lm;
        #pragma unroll
        for (int off = 16; off; off >>= 1) {
            float v2 = __shfl_xor_sync(0xffffffffu, v, off);
            int   m2 = __shfl_xor_sync(0xffffffffu, m, off);
            if (v2 > v || (v2 == v && m2 < m)) { v = v2; m = m2; }
        }
        if (lane == 0) idx_out[row * KNN + it] = m;
        if ((m & 31) == lane) {
            key[m] = NEG_INF;
            lv = NEG_INF; lm = -1;
            #pragma unroll
            for (int i = 0; i < 32; i++) {
                int mm = i * 32 + lane;
                float vv = key[mm];
                if (vv > lv) { lv = vv; lm = mm; }
            }
        }
        __syncwarp();
    }
}

// ---------------------------------------------------------------------------
// fold bn scale into weights:  w1s = s*W[:, :C],  wts = s*(W[:,C:] - W[:, :C])
// tb = s*bias + bn_b
// ---------------------------------------------------------------------------
__global__ void prep_w(const float* __restrict__ W, int C, int O,
                       const float* __restrict__ bias,
                       const float* __restrict__ bng, const float* __restrict__ bnb,
                       float* __restrict__ w1s, float* __restrict__ wts, float* __restrict__ tb)
{
    const float inv = 1.0f / sqrtf(1.00001f);
    int i = blockIdx.x * 256 + threadIdx.x;
    if (i < O * C) {
        int o = i / C, c = i - o * C;
        float s = bng[o] * inv;
        float wa = W[o * 2 * C + c];
        float wb = W[o * 2 * C + C + c];
        w1s[i] = s * wa;
        wts[i] = s * (wb - wa);
    }
    if (i < O) {
        float s = bng[i] * inv;
        tb[i] = s * (bias ? bias[i] : 0.f) + bnb[i];
    }
}

// ---------------------------------------------------------------------------
// gather + max + lrelu: out[p, off+o] = lrelu(max_k u[(b,idx_k), o] + t[p,o])
// blockDim = (CO, 256/CO)
// ---------------------------------------------------------------------------
__global__ void gathermax(const float* __restrict__ u, const float* __restrict__ t,
                          const int* __restrict__ idx, float* __restrict__ out,
                          int colOff, int CO)
{
    __shared__ int sidx[4][KNN];
    int ty = threadIdx.y, tx = threadIdx.x;
    int p = blockIdx.x * blockDim.y + ty;
    int b = p >> 10;
    if (tx < KNN) sidx[ty][tx] = idx[p * KNN + tx];
    __syncthreads();

    float tv = t[(size_t)p * CO + tx];
    float m = NEG_INF;
    #pragma unroll 4
    for (int k = 0; k < KNN; k++) {
        int j = sidx[ty][k];
        float v = u[(size_t)((b << 10) + j) * CO + tx] + tv;
        m = fmaxf(m, v);
    }
    m = (m >= 0.f) ? m : 0.01f * m;
    out[(size_t)p * 512 + colOff + tx] = m;
}

// ---------------------------------------------------------------------------
// global max pool over n with monotonic-uint float encoding
// ---------------------------------------------------------------------------
__global__ void zero_pool(unsigned* pool)
{
    int i = blockIdx.x * 256 + threadIdx.x;
    if (i < B_ * 1024) pool[i] = 0u;
}

__global__ void maxpool(const float* __restrict__ e, unsigned* __restrict__ pool)
{
    int o = blockIdx.x * 256 + threadIdx.x;
    int b = blockIdx.y, nz = blockIdx.z;
    const float* base = e + ((size_t)b * 1024 + nz * 64) * 1024 + o;
    float m = NEG_INF;
    #pragma unroll 8
    for (int n = 0; n < 64; n++) m = fmaxf(m, base[(size_t)n * 1024]);
    unsigned uu = __float_as_uint(m);
    uu = (uu >> 31) ? ~uu : (uu | 0x80000000u);
    atomicMax(&pool[b * 1024 + o], uu);
}

__device__ __forceinline__ float dec_pool(unsigned u)
{
    return (u & 0x80000000u) ? __uint_as_float(u & 0x7fffffffu) : __uint_as_float(~u);
}

// ---------------------------------------------------------------------------
// MLP head: warp per output element
// ---------------------------------------------------------------------------
__global__ void mlp1(const unsigned* __restrict__ pool, const float* __restrict__ w,
                     const float* __restrict__ g6, const float* __restrict__ b6,
                     float* __restrict__ y1)
{
    int b = blockIdx.y;
    int j = blockIdx.x * 4 + threadIdx.y;
    int lane = threadIdx.x;
    float s = 0.f;
    for (int c = lane; c < 1024; c += 32)
        s += dec_pool(pool[b * 1024 + c]) * w[j * 1024 + c];
    #pragma unroll
    for (int off = 16; off; off >>= 1) s += __shfl_xor_sync(0xffffffffu, s, off);
    if (lane == 0) {
        float v = s * (g6[j] * (1.0f / sqrtf(1.00001f))) + b6[j];
        y1[b * 512 + j] = (v >= 0.f) ? v : 0.01f * v;
    }
}

__global__ void mlp2(const float* __restrict__ y1, const float* __restrict__ w,
                     const float* __restrict__ wb, const float* __restrict__ g7,
                     const float* __restrict__ b7, float* __restrict__ y2)
{
    int b = blockIdx.y;
    int j = blockIdx.x * 4 + threadIdx.y;
    int lane = threadIdx.x;
    float s = 0.f;
    for (int c = lane; c < 512; c += 32) s += y1[b * 512 + c] * w[j * 512 + c];
    #pragma unroll
    for (int off = 16; off; off >>= 1) s += __shfl_xor_sync(0xffffffffu, s, off);
    if (lane == 0) {
        float v = (s + wb[j]) * (g7[j] * (1.0f / sqrtf(1.00001f))) + b7[j];
        y2[b * 256 + j] = (v >= 0.f) ? v : 0.01f * v;
    }
}

__global__ void mlp3(const float* __restrict__ y2, const float* __restrict__ w,
                     const float* __restrict__ wb, float* __restrict__ out)
{
    int b = blockIdx.y;
    int j = blockIdx.x * 4 + threadIdx.y;
    int lane = threadIdx.x;
    float s = 0.f;
    for (int c = lane; c < 256; c += 32) s += y2[b * 256 + c] * w[j * 256 + c];
    #pragma unroll
    for (int off = 16; off; off >>= 1) s += __shfl_xor_sync(0xffffffffu, s, off);
    if (lane == 0) out[b * 40 + j] = s + wb[j];
}

// ---------------------------------------------------------------------------
extern "C" void kernel_launch(void* const* d_in, const int* in_sizes, int n_in,
                              void* d_out, int out_size)
{
    const float* x        = (const float*)d_in[0];
    const float* conv1_w  = (const float*)d_in[1];
    const float* conv1_b  = (const float*)d_in[2];
    const float* bn1_g    = (const float*)d_in[3];
    const float* bn1_b    = (const float*)d_in[4];
    const float* conv2_w  = (const float*)d_in[5];
    const float* bn2_g    = (const float*)d_in[6];
    const float* bn2_b    = (const float*)d_in[7];
    const float* conv3_w  = (const float*)d_in[8];
    const float* bn3_g    = (const float*)d_in[9];
    const float* bn3_b    = (const float*)d_in[10];
    const float* conv4_w  = (const float*)d_in[11];
    const float* bn4_g    = (const float*)d_in[12];
    const float* bn4_b    = (const float*)d_in[13];
    const float* conv5_w  = (const float*)d_in[14];
    const float* lin1_w   = (const float*)d_in[15];
    const float* bn6_g    = (const float*)d_in[16];
    const float* bn6_b    = (const float*)d_in[17];
    const float* lin2_w   = (const float*)d_in[18];
    const float* lin2_b   = (const float*)d_in[19];
    const float* bn7_g    = (const float*)d_in[20];
    const float* bn7_b    = (const float*)d_in[21];
    const float* lin3_w   = (const float*)d_in[22];
    const float* lin3_b   = (const float*)d_in[23];

    float *xc, *inner, *u, *t, *xxp, *w1s, *wts, *tb, *y1, *y2;
    int* idx; unsigned* pool;
    cudaGetSymbolAddress((void**)&xc,    g_xc);
    cudaGetSymbolAddress((void**)&inner, g_inner);
    cudaGetSymbolAddress((void**)&u,     g_u);
    cudaGetSymbolAddress((void**)&t,     g_t);
    cudaGetSymbolAddress((void**)&xxp,   g_xx);
    cudaGetSymbolAddress((void**)&idx,   g_idx);
    cudaGetSymbolAddress((void**)&w1s,   g_w1s);
    cudaGetSymbolAddress((void**)&wts,   g_wts);
    cudaGetSymbolAddress((void**)&tb,    g_tb);
    cudaGetSymbolAddress((void**)&pool,  g_pool);
    cudaGetSymbolAddress((void**)&y1,    g_y1);
    cudaGetSymbolAddress((void**)&y2,    g_y2);

    struct Layer {
        const float* in; int lda; int Cin; int Cout; int off;
        const float* W; const float* bias; const float* g; const float* bb;
    };
    Layer L[4] = {
        { x,        3,   3,   64,   0, conv1_w, conv1_b, bn1_g, bn1_b },
        { xc + 0,   512, 64,  64,  64, conv2_w, nullptr, bn2_g, bn2_b },
        { xc + 64,  512, 64,  128, 128, conv3_w, nullptr, bn3_g, bn3_b },
        { xc + 128, 512, 128, 256, 256, conv4_w, nullptr, bn4_g, bn4_b },
    };

    zero_pool<<<32, 256>>>(pool);

    for (int l = 0; l < 4; l++) {
        const Layer& a = L[l];
        long long sIn = (long long)N_ * a.lda;

        // 1. squared norms
        xx_kernel<<<PTS / 8, 256>>>(a.in, a.lda, a.Cin, xxp);

        // 2. batched inner-product GEMM: inner[b,n,m] = x_n . x_m
        gemm_nt<<<dim3(N_ / BN, N_ / BM, B_), 256>>>(
            a.in, a.lda, sIn, a.in, a.lda, sIn,
            inner, N_, (long long)N_ * N_, a.Cin, nullptr);

        // 3. top-20 per row
        topk_kernel<<<PTS / 8, 256>>>(inner, xxp, idx);

        // 4. fold bn into weights
        prep_w<<<(a.Cout * a.Cin + 255) / 256, 256>>>(
            a.W, a.Cin, a.Cout, a.bias, a.g, a.bb, w1s, wts, tb);

        // 5. u = x @ (s*W_a)^T ; t = x @ (s*(W_b-W_a))^T + tb
        gemm_nt<<<dim3(a.Cout / BN, PTS / BM, 1), 256>>>(
            a.in, a.lda, 0, w1s, a.Cin, 0, u, a.Cout, 0, a.Cin, nullptr);
        gemm_nt<<<dim3(a.Cout / BN, PTS / BM, 1), 256>>>(
            a.in, a.lda, 0, wts, a.Cin, 0, t, a.Cout, 0, a.Cin, tb);

        // 6. gather + max + lrelu -> concat buffer column slice
        int ppb = 256 / a.Cout;
        gathermax<<<PTS / ppb, dim3(a.Cout, ppb)>>>(u, t, idx, xc, a.off, a.Cout);
    }

    // conv5: e[p,o] = xc[p,:512] . conv5_w[o,:512]
    gemm_nt<<<dim3(1024 / BN, PTS / BM, 1), 256>>>(
        xc, 512, 0, conv5_w, 512, 0, inner, 1024, 0, 512, nullptr);

    // global max pool over n
    maxpool<<<dim3(4, B_, 16), 256>>>(inner, pool);

    // MLP head
    mlp1<<<dim3(128, B_), dim3(32, 4)>>>(pool, lin1_w, bn6_g, bn6_b, y1);
    mlp2<<<dim3(64, B_),  dim3(32, 4)>>>(y1, lin2_w, lin2_b, bn7_g, bn7_b, y2);
    mlp3<<<dim3(10, B_),  dim3(32, 4)>>>(y2, lin3_w, lin3_b, (float*)d_out);
}

// round 3
// speedup vs baseline: 1.1205x; 1.1205x over previous
#include <cuda_runtime.h>
#include <cuda_bf16.h>
#include <cstdint>

// DGCNN forward. edge_conv reduced to per-point GEMMs:
//   out[b,n,o] = lrelu( max_k ( u[b,idx[b,n,k],o] + t[b,n,o] ) )
//   u = (s*W_a)@x ; t = (s*(W_b-W_a))@x + (s*bias + bn_b)
// GEMMs use packed fma.rn.f32x2 (2x fp32 throughput on sm_103a).

#define B_   8
#define N_   1024
#define PTS  (B_ * N_)
#define KNN  20
#define NEG_INF __int_as_float(0xff800000)

__device__ static float    g_xc[PTS * 512];
__device__ static float    g_inner[PTS * 1024];
__device__ static float    g_u[PTS * 256];
__device__ static float    g_t[PTS * 256];
__device__ static float    g_xx[PTS];
__device__ static int      g_idx[PTS * KNN];
__device__ static float    g_w1s[256 * 128];
__device__ static float    g_wts[256 * 128];
__device__ static float    g_tb[256];
__device__ static unsigned g_pool[B_ * 1024];
__device__ static float    g_y1[B_ * 512];
__device__ static float    g_y2[B_ * 256];

#define FMA_F32X2(d, a, b, c) \
    asm("fma.rn.f32x2 %0, %1, %2, %3;" : "=l"(d) : "l"(a), "l"(b), "l"(c))

__device__ __forceinline__ float f2lo(unsigned long long v) {
    return __uint_as_float((unsigned)(v & 0xffffffffull));
}
__device__ __forceinline__ float f2hi(unsigned long long v) {
    return __uint_as_float((unsigned)(v >> 32));
}

// ---------------------------------------------------------------------------
// FMA2 GEMM: C[m,n] = sum_k A[m,k]*B[n,k] (+bias[n])
// BM x BN block, BK=8, TH threads, 8x8 microtile (split 4+4 fragments).
// A is stored DUPLICATED in smem ({a,a} pairs) so fma.f32x2 needs no packing.
// M % BM == 0 and N % BN == 0 guaranteed by call sites; K arbitrary.
// ---------------------------------------------------------------------------
template<int BM, int BN, int TH>
__global__ void __launch_bounds__(TH, 2)
gemm_f2(const float* __restrict__ A, int lda, long long sA,
        const float* __restrict__ B, int ldb, long long sB,
        float* __restrict__ C, int ldc, long long sC,
        int K, const float* __restrict__ bias)
{
    constexpr int BK = 8;
    constexpr int LA = 2 * BM + 4;
    constexpr int LB = BN + 4;
    constexpr int NX = BN / 8;
    constexpr int NY = BM / 8;
    static_assert(NX * NY == TH, "thread count");
    constexpr int CA = (BM * 2) / TH;
    constexpr int CB = (BN * 2) / TH;
    static_assert(CA * TH == BM * 2 && CB * TH == BN * 2, "loader");

    __shared__ float As2[2][BK][LA];
    __shared__ float Bs[2][BK][LB];

    const int bz = blockIdx.z;
    A += bz * sA; B += bz * sB; C += bz * sC;
    const int m0 = blockIdx.y * BM;
    const int n0 = blockIdx.x * BN;
    const int tid = threadIdx.x;
    const int tx = tid % NX;
    const int ty = tid / NX;
    const bool a4 = ((lda & 3) == 0);
    const bool b4 = ((ldb & 3) == 0);

    unsigned long long acc[8][4];
    #pragma unroll
    for (int i = 0; i < 8; i++)
        #pragma unroll
        for (int j = 0; j < 4; j++) acc[i][j] = 0ull;

    float4 stA[CA], stB[CB];

    auto ldGA = [&](int k0) {
        #pragma unroll
        for (int i = 0; i < CA; i++) {
            int f4 = tid + i * TH;
            int row = f4 >> 1, kq = (f4 & 1) << 2;
            int k = k0 + kq;
            const float* p = A + (size_t)(m0 + row) * lda;
            float4 v;
            if (a4 && (k + 3) < K) v = *reinterpret_cast<const float4*>(p + k);
            else {
                v.x = (k     < K) ? p[k]     : 0.f;
                v.y = (k + 1 < K) ? p[k + 1] : 0.f;
                v.z = (k + 2 < K) ? p[k + 2] : 0.f;
                v.w = (k + 3 < K) ? p[k + 3] : 0.f;
            }
            stA[i] = v;
        }
    };
    auto ldGB = [&](int k0) {
        #pragma unroll
        for (int i = 0; i < CB; i++) {
            int f4 = tid + i * TH;
            int row = f4 >> 1, kq = (f4 & 1) << 2;
            int k = k0 + kq;
            const float* p = B + (size_t)(n0 + row) * ldb;
            float4 v;
            if (b4 && (k + 3) < K) v = *reinterpret_cast<const float4*>(p + k);
            else {
                v.x = (k     < K) ? p[k]     : 0.f;
                v.y = (k + 1 < K) ? p[k + 1] : 0.f;
                v.z = (k + 2 < K) ? p[k + 2] : 0.f;
                v.w = (k + 3 < K) ? p[k + 3] : 0.f;
            }
            stB[i] = v;
        }
    };
    auto stS = [&](int buf) {
        #pragma unroll
        for (int i = 0; i < CA; i++) {
            int f4 = tid + i * TH;
            int row = f4 >> 1, kq = (f4 & 1) << 2;
            float vv[4] = {stA[i].x, stA[i].y, stA[i].z, stA[i].w};
            #pragma unroll
            for (int j = 0; j < 4; j++)
                *reinterpret_cast<float2*>(&As2[buf][kq + j][2 * row]) =
                    make_float2(vv[j], vv[j]);
        }
        #pragma unroll
        for (int i = 0; i < CB; i++) {
            int f4 = tid + i * TH;
            int row = f4 >> 1, kq = (f4 & 1) << 2;
            Bs[buf][kq + 0][row] = stB[i].x;
            Bs[buf][kq + 1][row] = stB[i].y;
            Bs[buf][kq + 2][row] = stB[i].z;
            Bs[buf][kq + 3][row] = stB[i].w;
        }
    };

    const int nt = (K + BK - 1) / BK;
    ldGA(0); ldGB(0); stS(0);
    __syncthreads();

    for (int t = 0; t < nt; t++) {
        int buf = t & 1;
        if (t + 1 < nt) { ldGA((t + 1) * BK); ldGB((t + 1) * BK); }

        #pragma unroll
        for (int k = 0; k < BK; k++) {
            ulonglong2 a01 = *reinterpret_cast<const ulonglong2*>(&As2[buf][k][2 * (ty * 4)]);
            ulonglong2 a23 = *reinterpret_cast<const ulonglong2*>(&As2[buf][k][2 * (ty * 4) + 4]);
            ulonglong2 a45 = *reinterpret_cast<const ulonglong2*>(&As2[buf][k][2 * (BM / 2 + ty * 4)]);
            ulonglong2 a67 = *reinterpret_cast<const ulonglong2*>(&As2[buf][k][2 * (BM / 2 + ty * 4) + 4]);
            ulonglong2 b01 = *reinterpret_cast<const ulonglong2*>(&Bs[buf][k][tx * 4]);
            ulonglong2 b23 = *reinterpret_cast<const ulonglong2*>(&Bs[buf][k][BN / 2 + tx * 4]);
            unsigned long long av[8] = {a01.x, a01.y, a23.x, a23.y,
                                        a45.x, a45.y, a67.x, a67.y};
            unsigned long long bv[4] = {b01.x, b01.y, b23.x, b23.y};
            #pragma unroll
            for (int i = 0; i < 8; i++)
                #pragma unroll
                for (int j = 0; j < 4; j++)
                    FMA_F32X2(acc[i][j], av[i], bv[j], acc[i][j]);
        }

        if (t + 1 < nt) stS(buf ^ 1);
        __syncthreads();
    }

    float bx0 = 0.f, bx1 = 0.f, bx2 = 0.f, bx3 = 0.f;
    float by0 = 0.f, by1 = 0.f, by2 = 0.f, by3 = 0.f;
    if (bias) {
        const float* p0 = bias + n0 + tx * 4;
        const float* p1 = bias + n0 + BN / 2 + tx * 4;
        bx0 = p0[0]; bx1 = p0[1]; bx2 = p0[2]; bx3 = p0[3];
        by0 = p1[0]; by1 = p1[1]; by2 = p1[2]; by3 = p1[3];
    }
    #pragma unroll
    for (int i = 0; i < 8; i++) {
        int m = m0 + ((i < 4) ? (ty * 4 + i) : (BM / 2 + ty * 4 + i - 4));
        float4 o0, o1;
        o0.x = f2lo(acc[i][0]) + bx0; o0.y = f2hi(acc[i][0]) + bx1;
        o0.z = f2lo(acc[i][1]) + bx2; o0.w = f2hi(acc[i][1]) + bx3;
        o1.x = f2lo(acc[i][2]) + by0; o1.y = f2hi(acc[i][2]) + by1;
        o1.z = f2lo(acc[i][3]) + by2; o1.w = f2hi(acc[i][3]) + by3;
        *reinterpret_cast<float4*>(&C[(size_t)m * ldc + n0 + tx * 4]) = o0;
        *reinterpret_cast<float4*>(&C[(size_t)m * ldc + n0 + BN / 2 + tx * 4]) = o1;
    }
}

// ---------------------------------------------------------------------------
__global__ void xx_kernel(const float* __restrict__ X, int lda, int C, float* __restrict__ xx)
{
    int p = blockIdx.x * 8 + (threadIdx.x >> 5);
    int lane = threadIdx.x & 31;
    const float* r = X + (size_t)p * lda;
    float s = 0.f;
    for (int c = lane; c < C; c += 32) { float v = r[c]; s += v * v; }
    #pragma unroll
    for (int off = 16; off; off >>= 1) s += __shfl_xor_sync(0xffffffffu, s, off);
    if (lane == 0) xx[p] = s;
}

// ---------------------------------------------------------------------------
// top-20: warp per row. smem holds FULL 32-bit monotonic key per element.
// Register cache: per-lane top-2 of packed u64 = (key << 10) | (1023 - m)
// (exact key, exact low-index tie-break). Lazy smem rescan on cache empty.
// ---------------------------------------------------------------------------
__device__ __forceinline__ unsigned long long tk_pack(unsigned key, int m) {
    return ((unsigned long long)key << 10) | (unsigned)(1023 - m);
}

__global__ void __launch_bounds__(256)
topk_kernel(const float* __restrict__ inner, const float* __restrict__ xx,
            int* __restrict__ idx_out)
{
    __shared__ unsigned s[8][N_];
    int wid  = threadIdx.x >> 5;
    int lane = threadIdx.x & 31;
    int row  = blockIdx.x * 8 + wid;
    int b    = row >> 10;
    unsigned* sw = s[wid];
    const float* r  = inner + (size_t)row * N_;
    const float* xb = xx + (b << 10);

    unsigned long long e1 = 0, e2 = 0;
    #pragma unroll 8
    for (int i = 0; i < 32; i++) {
        int m = i * 32 + lane;
        float v = 2.f * r[m] - xb[m];
        unsigned u = __float_as_uint(v);
        u = ((int)u < 0) ? ~u : (u | 0x80000000u);
        sw[m] = u;
        unsigned long long enc = tk_pack(u, m);
        if (enc > e1) { e2 = e1; e1 = enc; }
        else if (enc > e2) { e2 = enc; }
    }
    __syncwarp();

    for (int it = 0; it < KNN; it++) {
        unsigned long long w = e1;
        #pragma unroll
        for (int off = 16; off; off >>= 1) {
            unsigned long long o = __shfl_xor_sync(0xffffffffu, w, off);
            w = (o > w) ? o : w;
        }
        int m = 1023 - (int)(w & 1023u);
        if (lane == 0) idx_out[row * KNN + it] = m;
        if (e1 == w) {                 // unique owner (enc embeds index)
            sw[m] = 0;
            e1 = e2; e2 = 0;
            if (e1 == 0) {             // cache empty: rescan remaining
                unsigned long long best = 0;
                #pragma unroll 8
                for (int i = 0; i < 32; i++) {
                    int mm = i * 32 + lane;
                    unsigned vv = sw[mm];
                    if (vv) {
                        unsigned long long enc = tk_pack(vv, mm);
                        best = (enc > best) ? enc : best;
                    }
                }
                e1 = best;
            }
        }
        __syncwarp();
    }
}

// ---------------------------------------------------------------------------
__global__ void prep_w(const float* __restrict__ W, int C, int O,
                       const float* __restrict__ bias,
                       const float* __restrict__ bng, const float* __restrict__ bnb,
                       float* __restrict__ w1s, float* __restrict__ wts, float* __restrict__ tb)
{
    const float inv = 1.0f / sqrtf(1.00001f);
    int i = blockIdx.x * 256 + threadIdx.x;
    if (i < O * C) {
        int o = i / C, c = i - o * C;
        float s = bng[o] * inv;
        float wa = W[o * 2 * C + c];
        float wb = W[o * 2 * C + C + c];
        w1s[i] = s * wa;
        wts[i] = s * (wb - wa);
    }
    if (i < O) {
        float s = bng[i] * inv;
        tb[i] = s * (bias ? bias[i] : 0.f) + bnb[i];
    }
}

// ---------------------------------------------------------------------------
__global__ void gathermax(const float* __restrict__ u, const float* __restrict__ t,
                          const int* __restrict__ idx, float* __restrict__ out,
                          int colOff, int CO)
{
    __shared__ int sidx[4][KNN];
    int ty = threadIdx.y, tx = threadIdx.x;
    int p = blockIdx.x * blockDim.y + ty;
    int b = p >> 10;
    if (tx < KNN) sidx[ty][tx] = idx[p * KNN + tx];
    __syncthreads();

    float tv = t[(size_t)p * CO + tx];
    float m = NEG_INF;
    #pragma unroll 4
    for (int k = 0; k < KNN; k++) {
        int j = sidx[ty][k];
        float v = u[(size_t)((b << 10) + j) * CO + tx] + tv;
        m = fmaxf(m, v);
    }
    m = (m >= 0.f) ? m : 0.01f * m;
    out[(size_t)p * 512 + colOff + tx] = m;
}

// ---------------------------------------------------------------------------
__global__ void zero_pool(unsigned* pool)
{
    int i = blockIdx.x * 256 + threadIdx.x;
    if (i < B_ * 1024) pool[i] = 0u;
}

__global__ void maxpool(const float* __restrict__ e, unsigned* __restrict__ pool)
{
    int o = blockIdx.x * 256 + threadIdx.x;
    int b = blockIdx.y, nz = blockIdx.z;
    const float* base = e + ((size_t)b * 1024 + nz * 64) * 1024 + o;
    float m = NEG_INF;
    #pragma unroll 8
    for (int n = 0; n < 64; n++) m = fmaxf(m, base[(size_t)n * 1024]);
    unsigned uu = __float_as_uint(m);
    uu = (uu >> 31) ? ~uu : (uu | 0x80000000u);
    atomicMax(&pool[b * 1024 + o], uu);
}

__device__ __forceinline__ float dec_pool(unsigned u)
{
    return (u & 0x80000000u) ? __uint_as_float(u & 0x7fffffffu) : __uint_as_float(~u);
}

// ---------------------------------------------------------------------------
__global__ void mlp1(const unsigned* __restrict__ pool, const float* __restrict__ w,
                     const float* __restrict__ g6, const float* __restrict__ b6,
                     float* __restrict__ y1)
{
    int b = blockIdx.y;
    int j = blockIdx.x * 4 + threadIdx.y;
    int lane = threadIdx.x;
    float s = 0.f;
    for (int c = lane; c < 1024; c += 32)
        s += dec_pool(pool[b * 1024 + c]) * w[j * 1024 + c];
    #pragma unroll
    for (int off = 16; off; off >>= 1) s += __shfl_xor_sync(0xffffffffu, s, off);
    if (lane == 0) {
        float v = s * (g6[j] * (1.0f / sqrtf(1.00001f))) + b6[j];
        y1[b * 512 + j] = (v >= 0.f) ? v : 0.01f * v;
    }
}

__global__ void mlp2(const float* __restrict__ y1, const float* __restrict__ w,
                     const float* __restrict__ wb, const float* __restrict__ g7,
                     const float* __restrict__ b7, float* __restrict__ y2)
{
    int b = blockIdx.y;
    int j = blockIdx.x * 4 + threadIdx.y;
    int lane = threadIdx.x;
    float s = 0.f;
    for (int c = lane; c < 512; c += 32) s += y1[b * 512 + c] * w[j * 512 + c];
    #pragma unroll
    for (int off = 16; off; off >>= 1) s += __shfl_xor_sync(0xffffffffu, s, off);
    if (lane == 0) {
        float v = (s + wb[j]) * (g7[j] * (1.0f / sqrtf(1.00001f))) + b7[j];
        y2[b * 256 + j] = (v >= 0.f) ? v : 0.01f * v;
    }
}

__global__ void mlp3(const float* __restrict__ y2, const float* __restrict__ w,
                     const float* __restrict__ wb, float* __restrict__ out)
{
    int b = blockIdx.y;
    int j = blockIdx.x * 4 + threadIdx.y;
    int lane = threadIdx.x;
    float s = 0.f;
    for (int c = lane; c < 256; c += 32) s += y2[b * 256 + c] * w[j * 256 + c];
    #pragma unroll
    for (int off = 16; off; off >>= 1) s += __shfl_xor_sync(0xffffffffu, s, off);
    if (lane == 0) out[b * 40 + j] = s + wb[j];
}

// ---------------------------------------------------------------------------
extern "C" void kernel_launch(void* const* d_in, const int* in_sizes, int n_in,
                              void* d_out, int out_size)
{
    const float* x        = (const float*)d_in[0];
    const float* conv1_w  = (const float*)d_in[1];
    const float* conv1_b  = (const float*)d_in[2];
    const float* bn1_g    = (const float*)d_in[3];
    const float* bn1_b    = (const float*)d_in[4];
    const float* conv2_w  = (const float*)d_in[5];
    const float* bn2_g    = (const float*)d_in[6];
    const float* bn2_b    = (const float*)d_in[7];
    const float* conv3_w  = (const float*)d_in[8];
    const float* bn3_g    = (const float*)d_in[9];
    const float* bn3_b    = (const float*)d_in[10];
    const float* conv4_w  = (const float*)d_in[11];
    const float* bn4_g    = (const float*)d_in[12];
    const float* bn4_b    = (const float*)d_in[13];
    const float* conv5_w  = (const float*)d_in[14];
    const float* lin1_w   = (const float*)d_in[15];
    const float* bn6_g    = (const float*)d_in[16];
    const float* bn6_b    = (const float*)d_in[17];
    const float* lin2_w   = (const float*)d_in[18];
    const float* lin2_b   = (const float*)d_in[19];
    const float* bn7_g    = (const float*)d_in[20];
    const float* bn7_b    = (const float*)d_in[21];
    const float* lin3_w   = (const float*)d_in[22];
    const float* lin3_b   = (const float*)d_in[23];

    float *xc, *inner, *u, *t, *xxp, *w1s, *wts, *tb, *y1, *y2;
    int* idx; unsigned* pool;
    cudaGetSymbolAddress((void**)&xc,    g_xc);
    cudaGetSymbolAddress((void**)&inner, g_inner);
    cudaGetSymbolAddress((void**)&u,     g_u);
    cudaGetSymbolAddress((void**)&t,     g_t);
    cudaGetSymbolAddress((void**)&xxp,   g_xx);
    cudaGetSymbolAddress((void**)&idx,   g_idx);
    cudaGetSymbolAddress((void**)&w1s,   g_w1s);
    cudaGetSymbolAddress((void**)&wts,   g_wts);
    cudaGetSymbolAddress((void**)&tb,    g_tb);
    cudaGetSymbolAddress((void**)&pool,  g_pool);
    cudaGetSymbolAddress((void**)&y1,    g_y1);
    cudaGetSymbolAddress((void**)&y2,    g_y2);

    struct Layer {
        const float* in; int lda; int Cin; int Cout; int off;
        const float* W; const float* bias; const float* g; const float* bb;
    };
    Layer L[4] = {
        { x,        3,   3,   64,  0,   conv1_w, conv1_b, bn1_g, bn1_b },
        { xc + 0,   512, 64,  64,  64,  conv2_w, nullptr, bn2_g, bn2_b },
        { xc + 64,  512, 64,  128, 128, conv3_w, nullptr, bn3_g, bn3_b },
        { xc + 128, 512, 128, 256, 256, conv4_w, nullptr, bn4_g, bn4_b },
    };

    zero_pool<<<32, 256>>>(pool);

    for (int l = 0; l < 4; l++) {
        const Layer& a = L[l];
        long long sIn = (long long)N_ * a.lda;

        xx_kernel<<<PTS / 8, 256>>>(a.in, a.lda, a.Cin, xxp);

        // batched inner-product GEMM: inner[b,n,m] = x_n . x_m
        gemm_f2<128, 128, 256><<<dim3(N_ / 128, N_ / 128, B_), 256>>>(
            a.in, a.lda, sIn, a.in, a.lda, sIn,
            inner, N_, (long long)N_ * N_, a.Cin, nullptr);

        topk_kernel<<<PTS / 8, 256>>>(inner, xxp, idx);

        prep_w<<<(a.Cout * a.Cin + 255) / 256, 256>>>(
            a.W, a.Cin, a.Cout, a.bias, a.g, a.bb, w1s, wts, tb);

        // u = x @ (s*W_a)^T ; t = x @ (s*(W_b-W_a))^T + tb
        gemm_f2<128, 64, 128><<<dim3(a.Cout / 64, PTS / 128, 1), 128>>>(
            a.in, a.lda, 0, w1s, a.Cin, 0, u, a.Cout, 0, a.Cin, nullptr);
        gemm_f2<128, 64, 128><<<dim3(a.Cout / 64, PTS / 128, 1), 128>>>(
            a.in, a.lda, 0, wts, a.Cin, 0, t, a.Cout, 0, a.Cin, tb);

        int ppb = 256 / a.Cout;
        gathermax<<<PTS / ppb, dim3(a.Cout, ppb)>>>(u, t, idx, xc, a.off, a.Cout);
    }

    // conv5: e[p,o] = xc[p,:512] . conv5_w[o,:512]
    gemm_f2<128, 128, 256><<<dim3(1024 / 128, PTS / 128, 1), 256>>>(
        xc, 512, 0, conv5_w, 512, 0, inner, 1024, 0, 512, nullptr);

    maxpool<<<dim3(4, B_, 16), 256>>>(inner, pool);

    mlp1<<<dim3(128, B_), dim3(32, 4)>>>(pool, lin1_w, bn6_g, bn6_b, y1);
    mlp2<<<dim3(64, B_),  dim3(32, 4)>>>(y1, lin2_w, lin2_b, bn7_g, bn7_b, y2);
    mlp3<<<dim3(10, B_),  dim3(32, 4)>>>(y2, lin3_w, lin3_b, (float*)d_out);
}

// round 6
// speedup vs baseline: 1.4185x; 1.2659x over previous
#include <cuda_runtime.h>
#include <cuda_bf16.h>
#include <cstdint>

// DGCNN forward.
//   edge_conv:  out[b,n,o] = lrelu( max_k ( u[b,idx_k,o] + t[b,n,o] ) )
//   u = (s*W_a)@x ; t = (s*(W_b-W_a))@x + (s*bias + bn_b)
// KNN inner-product GEMMs: exact fp32 SIMT (top-k is discretely sensitive).
// u|t GEMMs (l2-l4) + conv5: bf16-split x3 mma.sync (continuous paths).

#define B_   8
#define N_   1024
#define PTS  (B_ * N_)
#define KNN  20
#define NEG_INF __int_as_float(0xff800000)

__device__ static float          g_xc[PTS * 512];       // fp32 features (exact)
__device__ static __nv_bfloat16  g_xch[PTS * 512];      // bf16 hi
__device__ static __nv_bfloat16  g_xcl[PTS * 512];      // bf16 lo
__device__ static float          g_inner[PTS * 1024];
__device__ static float          g_ut[PTS * 512];
__device__ static float          g_utw[512 * 128];
__device__ static __nv_bfloat16  g_utwh[512 * 128];
__device__ static __nv_bfloat16  g_utwl[512 * 128];
__device__ static __nv_bfloat16  g_c5h[1024 * 512];
__device__ static __nv_bfloat16  g_c5l[1024 * 512];
__device__ static float          g_tb[256];
__device__ static float          g_xx[PTS];
__device__ static int            g_idx[PTS * KNN];
__device__ static unsigned       g_pool[B_ * 1024];
__device__ static float          g_y1[B_ * 512];
__device__ static float          g_y2[B_ * 256];

__device__ __forceinline__ uint32_t smem_u32(const void* p) {
    uint32_t a;
    asm("{ .reg .u64 t; cvta.to.shared.u64 t, %1; cvt.u32.u64 %0, t; }"
        : "=r"(a) : "l"(p));
    return a;
}

#define LDSM_X4(r0, r1, r2, r3, addr) \
    asm volatile("ldmatrix.sync.aligned.m8n8.x4.shared.b16 {%0,%1,%2,%3}, [%4];" \
                 : "=r"(r0), "=r"(r1), "=r"(r2), "=r"(r3) : "r"(addr))

#define MMA_BF16(c, a, b0, b1) \
    asm volatile( \
        "mma.sync.aligned.m16n8k16.row.col.f32.bf16.bf16.f32 " \
        "{%0,%1,%2,%3}, {%4,%5,%6,%7}, {%8,%9}, {%0,%1,%2,%3};" \
        : "+f"((c)[0]), "+f"((c)[1]), "+f"((c)[2]), "+f"((c)[3]) \
        : "r"((a)[0]), "r"((a)[1]), "r"((a)[2]), "r"((a)[3]), \
          "r"(b0), "r"(b1))

// ---------------------------------------------------------------------------
// bf16-split mma.sync GEMM: C[m,n] = sum_k A[m,k]*B[n,k], fp32 accum.
// C = Ah.Bh + Ah.Bl + Al.Bh. Tile 128x128x32, 8 warps (64x32 each).
// ---------------------------------------------------------------------------
#define SKA       40
#define TILE_B    (128 * SKA * 2)
#define STAGE_B   (4 * TILE_B)
#define MMA_SMEM  (2 * STAGE_B)

__global__ void __launch_bounds__(256)
mma_gemm(const __nv_bfloat16* __restrict__ Ah, const __nv_bfloat16* __restrict__ Al,
         int lda, long long sA,
         const __nv_bfloat16* __restrict__ Bh, const __nv_bfloat16* __restrict__ Bl,
         int ldb, long long sB,
         float* __restrict__ C, int ldc, long long sC, int K)
{
    extern __shared__ char smem[];
    const uint32_t sb0 = smem_u32(smem);

    const int tid  = threadIdx.x;
    const int wid  = tid >> 5;
    const int lane = tid & 31;
    const int bz = blockIdx.z;
    Ah += bz * sA; Al += bz * sA; Bh += bz * sB; Bl += bz * sB;
    const int m0 = blockIdx.y * 128;
    const int n0 = blockIdx.x * 128;
    const int m_warp = (wid & 1) * 64;
    const int n_warp = (wid >> 1) * 32;

    float acc[4][4][4];
    #pragma unroll
    for (int i = 0; i < 4; i++)
        #pragma unroll
        for (int j = 0; j < 4; j++)
            #pragma unroll
            for (int q = 0; q < 4; q++) acc[i][j][q] = 0.f;

    uint4 stg[8];
    auto ldG = [&](int kc) {
        #pragma unroll
        for (int i = 0; i < 8; i++) {
            int u = tid + i * 256;
            int tile = u >> 9;
            int r = (u >> 2) & 127;
            int q = u & 3;
            const __nv_bfloat16* src;
            int ld_, r0;
            if (tile == 0)      { src = Ah; ld_ = lda; r0 = m0; }
            else if (tile == 1) { src = Al; ld_ = lda; r0 = m0; }
            else if (tile == 2) { src = Bh; ld_ = ldb; r0 = n0; }
            else                { src = Bl; ld_ = ldb; r0 = n0; }
            stg[i] = *reinterpret_cast<const uint4*>(
                src + (size_t)(r0 + r) * ld_ + kc + q * 8);
        }
    };
    auto stS = [&](int stage) {
        char* base = smem + stage * STAGE_B;
        #pragma unroll
        for (int i = 0; i < 8; i++) {
            int u = tid + i * 256;
            int tile = u >> 9;
            int r = (u >> 2) & 127;
            int q = u & 3;
            *reinterpret_cast<uint4*>(base + tile * TILE_B + r * (SKA * 2) + q * 16) = stg[i];
        }
    };

    const int nc = K >> 5;
    ldG(0); stS(0);
    __syncthreads();

    for (int c = 0; c < nc; c++) {
        int buf = c & 1;
        if (c + 1 < nc) ldG((c + 1) * 32);

        const uint32_t sb = sb0 + buf * STAGE_B;
        #pragma unroll
        for (int ks = 0; ks < 32; ks += 16) {
            uint32_t ah[4][4], al[4][4], bh[2][4], bl[2][4];
            const uint32_t lrow = (lane & 15);
            const uint32_t lcol = (lane >> 4) * 8;
            #pragma unroll
            for (int mt = 0; mt < 4; mt++) {
                uint32_t off = ((m_warp + mt * 16 + lrow) * SKA + ks + lcol) * 2;
                LDSM_X4(ah[mt][0], ah[mt][1], ah[mt][2], ah[mt][3], sb + off);
                LDSM_X4(al[mt][0], al[mt][1], al[mt][2], al[mt][3], sb + TILE_B + off);
            }
            #pragma unroll
            for (int np = 0; np < 2; np++) {
                uint32_t off = ((n_warp + np * 16 + lrow) * SKA + ks + lcol) * 2;
                LDSM_X4(bh[np][0], bh[np][1], bh[np][2], bh[np][3], sb + 2 * TILE_B + off);
                LDSM_X4(bl[np][0], bl[np][1], bl[np][2], bl[np][3], sb + 3 * TILE_B + off);
            }
            #pragma unroll
            for (int mt = 0; mt < 4; mt++)
                #pragma unroll
                for (int nt = 0; nt < 4; nt++) {
                    int np = nt >> 1, half = nt & 1;
                    MMA_BF16(acc[mt][nt], ah[mt], bh[np][half], bh[np][2 + half]);
                    MMA_BF16(acc[mt][nt], ah[mt], bl[np][half], bl[np][2 + half]);
                    MMA_BF16(acc[mt][nt], al[mt], bh[np][half], bh[np][2 + half]);
                }
        }

        if (c + 1 < nc) stS(buf ^ 1);
        __syncthreads();
    }

    #pragma unroll
    for (int mt = 0; mt < 4; mt++)
        #pragma unroll
        for (int nt = 0; nt < 4; nt++) {
            int rm = m0 + m_warp + mt * 16 + (lane >> 2);
            int cn = n0 + n_warp + nt * 8 + (lane & 3) * 2;
            *reinterpret_cast<float2*>(&C[(size_t)rm * ldc + cn]) =
                make_float2(acc[mt][nt][0], acc[mt][nt][1]);
            *reinterpret_cast<float2*>(&C[(size_t)(rm + 8) * ldc + cn]) =
                make_float2(acc[mt][nt][2], acc[mt][nt][3]);
        }
}

// ---------------------------------------------------------------------------
// fp32 SIMT GEMM (exact path): C[m,n] = sum_k A[m,k]*B[n,k]
// ---------------------------------------------------------------------------
#define FMA_F32X2(d, a, b, c) \
    asm("fma.rn.f32x2 %0, %1, %2, %3;" : "=l"(d) : "l"(a), "l"(b), "l"(c))
__device__ __forceinline__ float f2lo(unsigned long long v) {
    return __uint_as_float((unsigned)(v & 0xffffffffull));
}
__device__ __forceinline__ float f2hi(unsigned long long v) {
    return __uint_as_float((unsigned)(v >> 32));
}

template<int BM, int BN, int TH>
__global__ void __launch_bounds__(TH, 2)
gemm_f2(const float* __restrict__ A, int lda, long long sA,
        const float* __restrict__ B, int ldb, long long sB,
        float* __restrict__ C, int ldc, long long sC, int K)
{
    constexpr int BK = 8;
    constexpr int LA = 2 * BM + 4;
    constexpr int LB = BN + 4;
    constexpr int NX = BN / 8;
    constexpr int NY = BM / 8;
    static_assert(NX * NY == TH, "threads");
    constexpr int CA = (BM * 2) / TH;
    constexpr int CB = (BN * 2) / TH;

    __shared__ float As2[2][BK][LA];
    __shared__ float Bs[2][BK][LB];

    const int bz = blockIdx.z;
    A += bz * sA; B += bz * sB; C += bz * sC;
    const int m0 = blockIdx.y * BM;
    const int n0 = blockIdx.x * BN;
    const int tid = threadIdx.x;
    const int tx = tid % NX;
    const int ty = tid / NX;
    const bool a4 = ((lda & 3) == 0);
    const bool b4 = ((ldb & 3) == 0);

    unsigned long long acc[8][4];
    #pragma unroll
    for (int i = 0; i < 8; i++)
        #pragma unroll
        for (int j = 0; j < 4; j++) acc[i][j] = 0ull;

    float4 stA[CA], stB[CB];
    auto ldGA = [&](int k0) {
        #pragma unroll
        for (int i = 0; i < CA; i++) {
            int f4 = tid + i * TH;
            int row = f4 >> 1, kq = (f4 & 1) << 2;
            int k = k0 + kq;
            const float* p = A + (size_t)(m0 + row) * lda;
            float4 v;
            if (a4 && (k + 3) < K) v = *reinterpret_cast<const float4*>(p + k);
            else {
                v.x = (k     < K) ? p[k]     : 0.f;
                v.y = (k + 1 < K) ? p[k + 1] : 0.f;
                v.z = (k + 2 < K) ? p[k + 2] : 0.f;
                v.w = (k + 3 < K) ? p[k + 3] : 0.f;
            }
            stA[i] = v;
        }
    };
    auto ldGB = [&](int k0) {
        #pragma unroll
        for (int i = 0; i < CB; i++) {
            int f4 = tid + i * TH;
            int row = f4 >> 1, kq = (f4 & 1) << 2;
            int k = k0 + kq;
            const float* p = B + (size_t)(n0 + row) * ldb;
            float4 v;
            if (b4 && (k + 3) < K) v = *reinterpret_cast<const float4*>(p + k);
            else {
                v.x = (k     < K) ? p[k]     : 0.f;
                v.y = (k + 1 < K) ? p[k + 1] : 0.f;
                v.z = (k + 2 < K) ? p[k + 2] : 0.f;
                v.w = (k + 3 < K) ? p[k + 3] : 0.f;
            }
            stB[i] = v;
        }
    };
    auto stS = [&](int buf) {
        #pragma unroll
        for (int i = 0; i < CA; i++) {
            int f4 = tid + i * TH;
            int row = f4 >> 1, kq = (f4 & 1) << 2;
            float vv[4] = {stA[i].x, stA[i].y, stA[i].z, stA[i].w};
            #pragma unroll
            for (int j = 0; j < 4; j++)
                *reinterpret_cast<float2*>(&As2[buf][kq + j][2 * row]) =
                    make_float2(vv[j], vv[j]);
        }
        #pragma unroll
        for (int i = 0; i < CB; i++) {
            int f4 = tid + i * TH;
            int row = f4 >> 1, kq = (f4 & 1) << 2;
            Bs[buf][kq + 0][row] = stB[i].x;
            Bs[buf][kq + 1][row] = stB[i].y;
            Bs[buf][kq + 2][row] = stB[i].z;
            Bs[buf][kq + 3][row] = stB[i].w;
        }
    };

    const int nt = (K + BK - 1) / BK;
    ldGA(0); ldGB(0); stS(0);
    __syncthreads();

    for (int t = 0; t < nt; t++) {
        int buf = t & 1;
        if (t + 1 < nt) { ldGA((t + 1) * BK); ldGB((t + 1) * BK); }
        #pragma unroll
        for (int k = 0; k < BK; k++) {
            ulonglong2 a01 = *reinterpret_cast<const ulonglong2*>(&As2[buf][k][2 * (ty * 4)]);
            ulonglong2 a23 = *reinterpret_cast<const ulonglong2*>(&As2[buf][k][2 * (ty * 4) + 4]);
            ulonglong2 a45 = *reinterpret_cast<const ulonglong2*>(&As2[buf][k][2 * (BM / 2 + ty * 4)]);
            ulonglong2 a67 = *reinterpret_cast<const ulonglong2*>(&As2[buf][k][2 * (BM / 2 + ty * 4) + 4]);
            ulonglong2 b01 = *reinterpret_cast<const ulonglong2*>(&Bs[buf][k][tx * 4]);
            ulonglong2 b23 = *reinterpret_cast<const ulonglong2*>(&Bs[buf][k][BN / 2 + tx * 4]);
            unsigned long long av[8] = {a01.x, a01.y, a23.x, a23.y,
                                        a45.x, a45.y, a67.x, a67.y};
            unsigned long long bv[4] = {b01.x, b01.y, b23.x, b23.y};
            #pragma unroll
            for (int i = 0; i < 8; i++)
                #pragma unroll
                for (int j = 0; j < 4; j++)
                    FMA_F32X2(acc[i][j], av[i], bv[j], acc[i][j]);
        }
        if (t + 1 < nt) stS(buf ^ 1);
        __syncthreads();
    }

    #pragma unroll
    for (int i = 0; i < 8; i++) {
        int m = m0 + ((i < 4) ? (ty * 4 + i) : (BM / 2 + ty * 4 + i - 4));
        float4 o0, o1;
        o0.x = f2lo(acc[i][0]); o0.y = f2hi(acc[i][0]);
        o0.z = f2lo(acc[i][1]); o0.w = f2hi(acc[i][1]);
        o1.x = f2lo(acc[i][2]); o1.y = f2hi(acc[i][2]);
        o1.z = f2lo(acc[i][3]); o1.w = f2hi(acc[i][3]);
        *reinterpret_cast<float4*>(&C[(size_t)m * ldc + n0 + tx * 4]) = o0;
        *reinterpret_cast<float4*>(&C[(size_t)m * ldc + n0 + BN / 2 + tx * 4]) = o1;
    }
}

// ---------------------------------------------------------------------------
__global__ void xx_kernel(const float* __restrict__ X, int lda, int C, float* __restrict__ xx)
{
    int p = blockIdx.x * 8 + (threadIdx.x >> 5);
    int lane = threadIdx.x & 31;
    const float* r = X + (size_t)p * lda;
    float s = 0.f;
    for (int c = lane; c < C; c += 32) { float v = r[c]; s += v * v; }
    #pragma unroll
    for (int off = 16; off; off >>= 1) s += __shfl_xor_sync(0xffffffffu, s, off);
    if (lane == 0) xx[p] = s;
}

// ---------------------------------------------------------------------------
// top-20: warp per row, full 32-bit key in smem, per-lane top-2 u64 cache.
// ---------------------------------------------------------------------------
__device__ __forceinline__ unsigned long long tk_pack(unsigned key, int m) {
    return ((unsigned long long)key << 10) | (unsigned)(1023 - m);
}

__global__ void __launch_bounds__(256)
topk_kernel(const float* __restrict__ inner, const float* __restrict__ xx,
            int* __restrict__ idx_out)
{
    __shared__ unsigned s[8][N_];
    int wid  = threadIdx.x >> 5;
    int lane = threadIdx.x & 31;
    int row  = blockIdx.x * 8 + wid;
    int b    = row >> 10;
    unsigned* sw = s[wid];
    const float* r  = inner + (size_t)row * N_;
    const float* xb = xx + (b << 10);

    unsigned long long e1 = 0, e2 = 0;
    #pragma unroll 8
    for (int i = 0; i < 32; i++) {
        int m = i * 32 + lane;
        float v = 2.f * r[m] - xb[m];
        unsigned u = __float_as_uint(v);
        u = ((int)u < 0) ? ~u : (u | 0x80000000u);
        sw[m] = u;
        unsigned long long enc = tk_pack(u, m);
        if (enc > e1) { e2 = e1; e1 = enc; }
        else if (enc > e2) { e2 = enc; }
    }
    __syncwarp();

    for (int it = 0; it < KNN; it++) {
        unsigned long long w = e1;
        #pragma unroll
        for (int off = 16; off; off >>= 1) {
            unsigned long long o = __shfl_xor_sync(0xffffffffu, w, off);
            w = (o > w) ? o : w;
        }
        int m = 1023 - (int)(w & 1023u);
        if (lane == 0) idx_out[row * KNN + it] = m;
        if (e1 == w) {
            sw[m] = 0;
            e1 = e2; e2 = 0;
            if (e1 == 0) {
                unsigned long long best = 0;
                #pragma unroll 8
                for (int i = 0; i < 32; i++) {
                    int mm = i * 32 + lane;
                    unsigned vv = sw[mm];
                    if (vv) {
                        unsigned long long enc = tk_pack(vv, mm);
                        best = (enc > best) ? enc : best;
                    }
                }
                e1 = best;
            }
        }
        __syncwarp();
    }
}

// ---------------------------------------------------------------------------
__device__ __forceinline__ void split_store(float v, __nv_bfloat16* h, __nv_bfloat16* l,
                                            size_t i)
{
    __nv_bfloat16 hb = __float2bfloat16(v);
    h[i] = hb;
    l[i] = __float2bfloat16(v - __bfloat162float(hb));
}

// combined weights: rows [0,O) = s*W_a (u), rows [O,2O) = s*(W_b-W_a) (t)
__global__ void prep_w(const float* __restrict__ W, int C, int O,
                       const float* __restrict__ bias,
                       const float* __restrict__ bng, const float* __restrict__ bnb,
                       float* __restrict__ utw,
                       __nv_bfloat16* __restrict__ utwh, __nv_bfloat16* __restrict__ utwl,
                       float* __restrict__ tb)
{
    const float inv = 1.0f / sqrtf(1.00001f);
    int i = blockIdx.x * 256 + threadIdx.x;
    if (i < O * C) {
        int o = i / C, c = i - o * C;
        float s = bng[o] * inv;
        float wa = W[o * 2 * C + c];
        float wb = W[o * 2 * C + C + c];
        float vu = s * wa;
        float vt = s * (wb - wa);
        utw[(size_t)o * C + c] = vu;
        utw[(size_t)(O + o) * C + c] = vt;
        split_store(vu, utwh, utwl, (size_t)o * C + c);
        split_store(vt, utwh, utwl, (size_t)(O + o) * C + c);
    }
    if (i < O) {
        float s = bng[i] * inv;
        tb[i] = s * (bias ? bias[i] : 0.f) + bnb[i];
    }
}

__global__ void prep_c5(const float* __restrict__ W,
                        __nv_bfloat16* __restrict__ h, __nv_bfloat16* __restrict__ l)
{
    int i = blockIdx.x * 256 + threadIdx.x;
    if (i < 1024 * 512) split_store(W[i], h, l, i);
}

// ---------------------------------------------------------------------------
// gather + max + lrelu; writes fp32 feature + bf16 hi/lo copies.
// ut layout: [p][2*CO]: cols [0,CO)=u, [CO,2CO)=t.
// ---------------------------------------------------------------------------
__global__ void gathermax(const float* __restrict__ ut, const float* __restrict__ tb,
                          const int* __restrict__ idx,
                          float* __restrict__ xc,
                          __nv_bfloat16* __restrict__ xch, __nv_bfloat16* __restrict__ xcl,
                          int colOff, int CO)
{
    __shared__ int sidx[4][KNN];
    int ty = threadIdx.y, tx = threadIdx.x;
    int p = blockIdx.x * blockDim.y + ty;
    int b = p >> 10;
    if (tx < KNN) sidx[ty][tx] = idx[p * KNN + tx];
    __syncthreads();

    int st = 2 * CO;
    float tv = ut[(size_t)p * st + CO + tx] + tb[tx];
    float m = NEG_INF;
    #pragma unroll 4
    for (int k = 0; k < KNN; k++) {
        int j = sidx[ty][k];
        float v = ut[(size_t)((b << 10) + j) * st + tx] + tv;
        m = fmaxf(m, v);
    }
    m = (m >= 0.f) ? m : 0.01f * m;
    size_t o = (size_t)p * 512 + colOff + tx;
    xc[o] = m;
    split_store(m, xch, xcl, o);
}

// ---------------------------------------------------------------------------
__global__ void zero_pool(unsigned* pool)
{
    int i = blockIdx.x * 256 + threadIdx.x;
    if (i < B_ * 1024) pool[i] = 0u;
}

__global__ void maxpool(const float* __restrict__ e, unsigned* __restrict__ pool)
{
    int o = blockIdx.x * 256 + threadIdx.x;
    int b = blockIdx.y, nz = blockIdx.z;
    const float* base = e + ((size_t)b * 1024 + nz * 64) * 1024 + o;
    float m = NEG_INF;
    #pragma unroll 8
    for (int n = 0; n < 64; n++) m = fmaxf(m, base[(size_t)n * 1024]);
    unsigned uu = __float_as_uint(m);
    uu = (uu >> 31) ? ~uu : (uu | 0x80000000u);
    atomicMax(&pool[b * 1024 + o], uu);
}

__device__ __forceinline__ float dec_pool(unsigned u)
{
    return (u & 0x80000000u) ? __uint_as_float(u & 0x7fffffffu) : __uint_as_float(~u);
}

// ---------------------------------------------------------------------------
__global__ void mlp1(const unsigned* __restrict__ pool, const float* __restrict__ w,
                     const float* __restrict__ g6, const float* __restrict__ b6,
                     float* __restrict__ y1)
{
    int b = blockIdx.y;
    int j = blockIdx.x * 4 + threadIdx.y;
    int lane = threadIdx.x;
    float s = 0.f;
    for (int c = lane; c < 1024; c += 32)
        s += dec_pool(pool[b * 1024 + c]) * w[j * 1024 + c];
    #pragma unroll
    for (int off = 16; off; off >>= 1) s += __shfl_xor_sync(0xffffffffu, s, off);
    if (lane == 0) {
        float v = s * (g6[j] * (1.0f / sqrtf(1.00001f))) + b6[j];
        y1[b * 512 + j] = (v >= 0.f) ? v : 0.01f * v;
    }
}

__global__ void mlp2(const float* __restrict__ y1, const float* __restrict__ w,
                     const float* __restrict__ wb, const float* __restrict__ g7,
                     const float* __restrict__ b7, float* __restrict__ y2)
{
    int b = blockIdx.y;
    int j = blockIdx.x * 4 + threadIdx.y;
    int lane = threadIdx.x;
    float s = 0.f;
    for (int c = lane; c < 512; c += 32) s += y1[b * 512 + c] * w[j * 512 + c];
    #pragma unroll
    for (int off = 16; off; off >>= 1) s += __shfl_xor_sync(0xffffffffu, s, off);
    if (lane == 0) {
        float v = (s + wb[j]) * (g7[j] * (1.0f / sqrtf(1.00001f))) + b7[j];
        y2[b * 256 + j] = (v >= 0.f) ? v : 0.01f * v;
    }
}

__global__ void mlp3(const float* __restrict__ y2, const float* __restrict__ w,
                     const float* __restrict__ wb, float* __restrict__ out)
{
    int b = blockIdx.y;
    int j = blockIdx.x * 4 + threadIdx.y;
    int lane = threadIdx.x;
    float s = 0.f;
    for (int c = lane; c < 256; c += 32) s += y2[b * 256 + c] * w[j * 256 + c];
    #pragma unroll
    for (int off = 16; off; off >>= 1) s += __shfl_xor_sync(0xffffffffu, s, off);
    if (lane == 0) out[b * 40 + j] = s + wb[j];
}

// ---------------------------------------------------------------------------
extern "C" void kernel_launch(void* const* d_in, const int* in_sizes, int n_in,
                              void* d_out, int out_size)
{
    const float* x        = (const float*)d_in[0];
    const float* conv1_w  = (const float*)d_in[1];
    const float* conv1_b  = (const float*)d_in[2];
    const float* bn1_g    = (const float*)d_in[3];
    const float* bn1_b    = (const float*)d_in[4];
    const float* conv2_w  = (const float*)d_in[5];
    const float* bn2_g    = (const float*)d_in[6];
    const float* bn2_b    = (const float*)d_in[7];
    const float* conv3_w  = (const float*)d_in[8];
    const float* bn3_g    = (const float*)d_in[9];
    const float* bn3_b    = (const float*)d_in[10];
    const float* conv4_w  = (const float*)d_in[11];
    const float* bn4_g    = (const float*)d_in[12];
    const float* bn4_b    = (const float*)d_in[13];
    const float* conv5_w  = (const float*)d_in[14];
    const float* lin1_w   = (const float*)d_in[15];
    const float* bn6_g    = (const float*)d_in[16];
    const float* bn6_b    = (const float*)d_in[17];
    const float* lin2_w   = (const float*)d_in[18];
    const float* lin2_b   = (const float*)d_in[19];
    const float* bn7_g    = (const float*)d_in[20];
    const float* bn7_b    = (const float*)d_in[21];
    const float* lin3_w   = (const float*)d_in[22];
    const float* lin3_b   = (const float*)d_in[23];

    float *xc, *inner, *ut, *utw, *tb, *xxp, *y1, *y2;
    __nv_bfloat16 *xch, *xcl, *utwh, *utwl, *c5h, *c5l;
    int* idx; unsigned* pool;
    cudaGetSymbolAddress((void**)&xc,    g_xc);
    cudaGetSymbolAddress((void**)&inner, g_inner);
    cudaGetSymbolAddress((void**)&xch,   g_xch);
    cudaGetSymbolAddress((void**)&xcl,   g_xcl);
    cudaGetSymbolAddress((void**)&ut,    g_ut);
    cudaGetSymbolAddress((void**)&utw,   g_utw);
    cudaGetSymbolAddress((void**)&utwh,  g_utwh);
    cudaGetSymbolAddress((void**)&utwl,  g_utwl);
    cudaGetSymbolAddress((void**)&c5h,   g_c5h);
    cudaGetSymbolAddress((void**)&c5l,   g_c5l);
    cudaGetSymbolAddress((void**)&tb,    g_tb);
    cudaGetSymbolAddress((void**)&xxp,   g_xx);
    cudaGetSymbolAddress((void**)&idx,   g_idx);
    cudaGetSymbolAddress((void**)&pool,  g_pool);
    cudaGetSymbolAddress((void**)&y1,    g_y1);
    cudaGetSymbolAddress((void**)&y2,    g_y2);

    cudaFuncSetAttribute(mma_gemm, cudaFuncAttributeMaxDynamicSharedMemorySize, MMA_SMEM);

    struct Layer {
        int inOff; int Cin; int Cout; int outOff;
        const float* W; const float* bias; const float* g; const float* bb;
    };
    Layer L[4] = {
        { -1,  3,   64,  0,   conv1_w, conv1_b, bn1_g, bn1_b },
        { 0,   64,  64,  64,  conv2_w, nullptr, bn2_g, bn2_b },
        { 64,  64,  128, 128, conv3_w, nullptr, bn3_g, bn3_b },
        { 128, 128, 256, 256, conv4_w, nullptr, bn4_g, bn4_b },
    };

    zero_pool<<<32, 256>>>(pool);

    for (int l = 0; l < 4; l++) {
        const Layer& a = L[l];
        const float* fin = (l == 0) ? x : (xc + a.inOff);
        int lda = (l == 0) ? 3 : 512;

        xx_kernel<<<PTS / 8, 256>>>(fin, lda, a.Cin, xxp);

        // inner[b,n,m] = x_n . x_m — EXACT fp32 (top-k sensitivity)
        gemm_f2<128, 128, 256><<<dim3(8, 8, B_), 256>>>(
            fin, lda, (long long)N_ * lda, fin, lda, (long long)N_ * lda,
            inner, N_, (long long)N_ * N_, a.Cin);

        topk_kernel<<<PTS / 8, 256>>>(inner, xxp, idx);

        prep_w<<<(a.Cout * a.Cin + 255) / 256, 256>>>(
            a.W, a.Cin, a.Cout, a.bias, a.g, a.bb, utw, utwh, utwl, tb);

        // combined u|t GEMM: C[p, 0..2Cout)
        if (l == 0) {
            gemm_f2<128, 64, 128><<<dim3(2, PTS / 128, 1), 128>>>(
                x, 3, 0, utw, 3, 0, ut, 128, 0, 3);
        } else {
            mma_gemm<<<dim3(2 * a.Cout / 128, PTS / 128, 1), 256, MMA_SMEM>>>(
                xch + a.inOff, xcl + a.inOff, 512, 0,
                utwh, utwl, a.Cin, 0,
                ut, 2 * a.Cout, 0, a.Cin);
        }

        int ppb = 256 / a.Cout;
        if (ppb < 1) ppb = 1;
        gathermax<<<PTS / ppb, dim3(a.Cout, ppb)>>>(ut, tb, idx, xc, xch, xcl,
                                                    a.outOff, a.Cout);
    }

    // conv5: e[p,o] = xc[p,:512] . conv5_w[o,:512]  (continuous -> MMA)
    prep_c5<<<(1024 * 512 + 255) / 256, 256>>>(conv5_w, c5h, c5l);
    mma_gemm<<<dim3(8, PTS / 128, 1), 256, MMA_SMEM>>>(
        xch, xcl, 512, 0, c5h, c5l, 512, 0, inner, 1024, 0, 512);

    maxpool<<<dim3(4, B_, 16), 256>>>(inner, pool);

    mlp1<<<dim3(128, B_), dim3(32, 4)>>>(pool, lin1_w, bn6_g, bn6_b, y1);
    mlp2<<<dim3(64, B_),  dim3(32, 4)>>>(y1, lin2_w, lin2_b, bn7_g, bn7_b, y2);
    mlp3<<<dim3(10, B_),  dim3(32, 4)>>>(y2, lin3_w, lin3_b, (float*)d_out);
}

// round 7
// speedup vs baseline: 1.6195x; 1.1416x over previous
#include <cuda_runtime.h>
#include <cuda_bf16.h>
#include <cstdint>

// DGCNN forward.
//   edge_conv:  out[b,n,o] = lrelu( max_k ( u[b,idx_k,o] + t[b,n,o] ) )
//   u = (s*W_a)@x ; t = (s*(W_b-W_a))@x + (s*bias + bn_b)
// KNN inner GEMMs: exact fp32 SIMT, symmetric (lower triangle + mirror store).
// u|t GEMMs (l2-l4) + conv5: bf16-split x3 mma.sync (continuous paths).

#define B_   8
#define N_   1024
#define PTS  (B_ * N_)
#define KNN  20
#define NEG_INF __int_as_float(0xff800000)

__device__ static float          g_xc[PTS * 512];
__device__ static __nv_bfloat16  g_xch[PTS * 512];
__device__ static __nv_bfloat16  g_xcl[PTS * 512];
__device__ static float          g_inner[PTS * 1024];
__device__ static float          g_ut[PTS * 512];
__device__ static float          g_utw[512 * 128];
__device__ static __nv_bfloat16  g_utwh[512 * 128];
__device__ static __nv_bfloat16  g_utwl[512 * 128];
__device__ static __nv_bfloat16  g_c5h[1024 * 512];
__device__ static __nv_bfloat16  g_c5l[1024 * 512];
__device__ static float          g_tb[256];
__device__ static float          g_xx[PTS];
__device__ static int            g_idx[PTS * KNN];
__device__ static unsigned       g_pool[B_ * 1024];
__device__ static float          g_y1[B_ * 512];
__device__ static float          g_y2[B_ * 256];

__device__ __forceinline__ uint32_t smem_u32(const void* p) {
    uint32_t a;
    asm("{ .reg .u64 t; cvta.to.shared.u64 t, %1; cvt.u32.u64 %0, t; }"
        : "=r"(a) : "l"(p));
    return a;
}

__device__ __forceinline__ unsigned redux_max(unsigned v) {
    unsigned r;
    asm("redux.sync.max.u32 %0, %1, 0xffffffff;" : "=r"(r) : "r"(v));
    return r;
}

#define LDSM_X4(r0, r1, r2, r3, addr) \
    asm volatile("ldmatrix.sync.aligned.m8n8.x4.shared.b16 {%0,%1,%2,%3}, [%4];" \
                 : "=r"(r0), "=r"(r1), "=r"(r2), "=r"(r3) : "r"(addr))

#define MMA_BF16(c, a, b0, b1) \
    asm volatile( \
        "mma.sync.aligned.m16n8k16.row.col.f32.bf16.bf16.f32 " \
        "{%0,%1,%2,%3}, {%4,%5,%6,%7}, {%8,%9}, {%0,%1,%2,%3};" \
        : "+f"((c)[0]), "+f"((c)[1]), "+f"((c)[2]), "+f"((c)[3]) \
        : "r"((a)[0]), "r"((a)[1]), "r"((a)[2]), "r"((a)[3]), \
          "r"(b0), "r"(b1))

// ---------------------------------------------------------------------------
// bf16-split mma.sync GEMM (continuous paths only).
// ---------------------------------------------------------------------------
#define SKA       40
#define TILE_B    (128 * SKA * 2)
#define STAGE_B   (4 * TILE_B)
#define MMA_SMEM  (2 * STAGE_B)

__global__ void __launch_bounds__(256)
mma_gemm(const __nv_bfloat16* __restrict__ Ah, const __nv_bfloat16* __restrict__ Al,
         int lda, long long sA,
         const __nv_bfloat16* __restrict__ Bh, const __nv_bfloat16* __restrict__ Bl,
         int ldb, long long sB,
         float* __restrict__ C, int ldc, long long sC, int K)
{
    extern __shared__ char smem[];
    const uint32_t sb0 = smem_u32(smem);

    const int tid  = threadIdx.x;
    const int wid  = tid >> 5;
    const int lane = tid & 31;
    const int bz = blockIdx.z;
    Ah += bz * sA; Al += bz * sA; Bh += bz * sB; Bl += bz * sB;
    const int m0 = blockIdx.y * 128;
    const int n0 = blockIdx.x * 128;
    const int m_warp = (wid & 1) * 64;
    const int n_warp = (wid >> 1) * 32;

    float acc[4][4][4];
    #pragma unroll
    for (int i = 0; i < 4; i++)
        #pragma unroll
        for (int j = 0; j < 4; j++)
            #pragma unroll
            for (int q = 0; q < 4; q++) acc[i][j][q] = 0.f;

    uint4 stg[8];
    auto ldG = [&](int kc) {
        #pragma unroll
        for (int i = 0; i < 8; i++) {
            int u = tid + i * 256;
            int tile = u >> 9;
            int r = (u >> 2) & 127;
            int q = u & 3;
            const __nv_bfloat16* src;
            int ld_, r0;
            if (tile == 0)      { src = Ah; ld_ = lda; r0 = m0; }
            else if (tile == 1) { src = Al; ld_ = lda; r0 = m0; }
            else if (tile == 2) { src = Bh; ld_ = ldb; r0 = n0; }
            else                { src = Bl; ld_ = ldb; r0 = n0; }
            stg[i] = *reinterpret_cast<const uint4*>(
                src + (size_t)(r0 + r) * ld_ + kc + q * 8);
        }
    };
    auto stS = [&](int stage) {
        char* base = smem + stage * STAGE_B;
        #pragma unroll
        for (int i = 0; i < 8; i++) {
            int u = tid + i * 256;
            int tile = u >> 9;
            int r = (u >> 2) & 127;
            int q = u & 3;
            *reinterpret_cast<uint4*>(base + tile * TILE_B + r * (SKA * 2) + q * 16) = stg[i];
        }
    };

    const int nc = K >> 5;
    ldG(0); stS(0);
    __syncthreads();

    for (int c = 0; c < nc; c++) {
        int buf = c & 1;
        if (c + 1 < nc) ldG((c + 1) * 32);

        const uint32_t sb = sb0 + buf * STAGE_B;
        #pragma unroll
        for (int ks = 0; ks < 32; ks += 16) {
            uint32_t ah[4][4], al[4][4], bh[2][4], bl[2][4];
            const uint32_t lrow = (lane & 15);
            const uint32_t lcol = (lane >> 4) * 8;
            #pragma unroll
            for (int mt = 0; mt < 4; mt++) {
                uint32_t off = ((m_warp + mt * 16 + lrow) * SKA + ks + lcol) * 2;
                LDSM_X4(ah[mt][0], ah[mt][1], ah[mt][2], ah[mt][3], sb + off);
                LDSM_X4(al[mt][0], al[mt][1], al[mt][2], al[mt][3], sb + TILE_B + off);
            }
            #pragma unroll
            for (int np = 0; np < 2; np++) {
                uint32_t off = ((n_warp + np * 16 + lrow) * SKA + ks + lcol) * 2;
                LDSM_X4(bh[np][0], bh[np][1], bh[np][2], bh[np][3], sb + 2 * TILE_B + off);
                LDSM_X4(bl[np][0], bl[np][1], bl[np][2], bl[np][3], sb + 3 * TILE_B + off);
            }
            #pragma unroll
            for (int mt = 0; mt < 4; mt++)
                #pragma unroll
                for (int nt = 0; nt < 4; nt++) {
                    int np = nt >> 1, half = nt & 1;
                    MMA_BF16(acc[mt][nt], ah[mt], bh[np][half], bh[np][2 + half]);
                    MMA_BF16(acc[mt][nt], ah[mt], bl[np][half], bl[np][2 + half]);
                    MMA_BF16(acc[mt][nt], al[mt], bh[np][half], bh[np][2 + half]);
                }
        }

        if (c + 1 < nc) stS(buf ^ 1);
        __syncthreads();
    }

    #pragma unroll
    for (int mt = 0; mt < 4; mt++)
        #pragma unroll
        for (int nt = 0; nt < 4; nt++) {
            int rm = m0 + m_warp + mt * 16 + (lane >> 2);
            int cn = n0 + n_warp + nt * 8 + (lane & 3) * 2;
            *reinterpret_cast<float2*>(&C[(size_t)rm * ldc + cn]) =
                make_float2(acc[mt][nt][0], acc[mt][nt][1]);
            *reinterpret_cast<float2*>(&C[(size_t)(rm + 8) * ldc + cn]) =
                make_float2(acc[mt][nt][2], acc[mt][nt][3]);
        }
}

// ---------------------------------------------------------------------------
// fp32 SIMT GEMM machinery (exact path)
// ---------------------------------------------------------------------------
#define FMA_F32X2(d, a, b, c) \
    asm("fma.rn.f32x2 %0, %1, %2, %3;" : "=l"(d) : "l"(a), "l"(b), "l"(c))
__device__ __forceinline__ float f2lo(unsigned long long v) {
    return __uint_as_float((unsigned)(v & 0xffffffffull));
}
__device__ __forceinline__ float f2hi(unsigned long long v) {
    return __uint_as_float((unsigned)(v >> 32));
}

template<int BM, int BN, int TH>
__global__ void __launch_bounds__(TH, 2)
gemm_f2(const float* __restrict__ A, int lda, long long sA,
        const float* __restrict__ B, int ldb, long long sB,
        float* __restrict__ C, int ldc, long long sC, int K)
{
    constexpr int BK = 8;
    constexpr int LA = 2 * BM + 4;
    constexpr int LB = BN + 4;
    constexpr int NX = BN / 8;
    constexpr int NY = BM / 8;
    static_assert(NX * NY == TH, "threads");
    constexpr int CA = (BM * 2) / TH;
    constexpr int CB = (BN * 2) / TH;

    __shared__ float As2[2][BK][LA];
    __shared__ float Bs[2][BK][LB];

    const int bz = blockIdx.z;
    A += bz * sA; B += bz * sB; C += bz * sC;
    const int m0 = blockIdx.y * BM;
    const int n0 = blockIdx.x * BN;
    const int tid = threadIdx.x;
    const int tx = tid % NX;
    const int ty = tid / NX;
    const bool a4 = ((lda & 3) == 0);
    const bool b4 = ((ldb & 3) == 0);

    unsigned long long acc[8][4];
    #pragma unroll
    for (int i = 0; i < 8; i++)
        #pragma unroll
        for (int j = 0; j < 4; j++) acc[i][j] = 0ull;

    float4 stA[CA], stB[CB];
    auto ldGA = [&](int k0) {
        #pragma unroll
        for (int i = 0; i < CA; i++) {
            int f4 = tid + i * TH;
            int row = f4 >> 1, kq = (f4 & 1) << 2;
            int k = k0 + kq;
            const float* p = A + (size_t)(m0 + row) * lda;
            float4 v;
            if (a4 && (k + 3) < K) v = *reinterpret_cast<const float4*>(p + k);
            else {
                v.x = (k     < K) ? p[k]     : 0.f;
                v.y = (k + 1 < K) ? p[k + 1] : 0.f;
                v.z = (k + 2 < K) ? p[k + 2] : 0.f;
                v.w = (k + 3 < K) ? p[k + 3] : 0.f;
            }
            stA[i] = v;
        }
    };
    auto ldGB = [&](int k0) {
        #pragma unroll
        for (int i = 0; i < CB; i++) {
            int f4 = tid + i * TH;
            int row = f4 >> 1, kq = (f4 & 1) << 2;
            int k = k0 + kq;
            const float* p = B + (size_t)(n0 + row) * ldb;
            float4 v;
            if (b4 && (k + 3) < K) v = *reinterpret_cast<const float4*>(p + k);
            else {
                v.x = (k     < K) ? p[k]     : 0.f;
                v.y = (k + 1 < K) ? p[k + 1] : 0.f;
                v.z = (k + 2 < K) ? p[k + 2] : 0.f;
                v.w = (k + 3 < K) ? p[k + 3] : 0.f;
            }
            stB[i] = v;
        }
    };
    auto stS = [&](int buf) {
        #pragma unroll
        for (int i = 0; i < CA; i++) {
            int f4 = tid + i * TH;
            int row = f4 >> 1, kq = (f4 & 1) << 2;
            float vv[4] = {stA[i].x, stA[i].y, stA[i].z, stA[i].w};
            #pragma unroll
            for (int j = 0; j < 4; j++)
                *reinterpret_cast<float2*>(&As2[buf][kq + j][2 * row]) =
                    make_float2(vv[j], vv[j]);
        }
        #pragma unroll
        for (int i = 0; i < CB; i++) {
            int f4 = tid + i * TH;
            int row = f4 >> 1, kq = (f4 & 1) << 2;
            Bs[buf][kq + 0][row] = stB[i].x;
            Bs[buf][kq + 1][row] = stB[i].y;
            Bs[buf][kq + 2][row] = stB[i].z;
            Bs[buf][kq + 3][row] = stB[i].w;
        }
    };

    const int nt = (K + BK - 1) / BK;
    ldGA(0); ldGB(0); stS(0);
    __syncthreads();

    for (int t = 0; t < nt; t++) {
        int buf = t & 1;
        if (t + 1 < nt) { ldGA((t + 1) * BK); ldGB((t + 1) * BK); }
        #pragma unroll
        for (int k = 0; k < BK; k++) {
            ulonglong2 a01 = *reinterpret_cast<const ulonglong2*>(&As2[buf][k][2 * (ty * 4)]);
            ulonglong2 a23 = *reinterpret_cast<const ulonglong2*>(&As2[buf][k][2 * (ty * 4) + 4]);
            ulonglong2 a45 = *reinterpret_cast<const ulonglong2*>(&As2[buf][k][2 * (BM / 2 + ty * 4)]);
            ulonglong2 a67 = *reinterpret_cast<const ulonglong2*>(&As2[buf][k][2 * (BM / 2 + ty * 4) + 4]);
            ulonglong2 b01 = *reinterpret_cast<const ulonglong2*>(&Bs[buf][k][tx * 4]);
            ulonglong2 b23 = *reinterpret_cast<const ulonglong2*>(&Bs[buf][k][BN / 2 + tx * 4]);
            unsigned long long av[8] = {a01.x, a01.y, a23.x, a23.y,
                                        a45.x, a45.y, a67.x, a67.y};
            unsigned long long bv[4] = {b01.x, b01.y, b23.x, b23.y};
            #pragma unroll
            for (int i = 0; i < 8; i++)
                #pragma unroll
                for (int j = 0; j < 4; j++)
                    FMA_F32X2(acc[i][j], av[i], bv[j], acc[i][j]);
        }
        if (t + 1 < nt) stS(buf ^ 1);
        __syncthreads();
    }

    #pragma unroll
    for (int i = 0; i < 8; i++) {
        int m = m0 + ((i < 4) ? (ty * 4 + i) : (BM / 2 + ty * 4 + i - 4));
        float4 o0, o1;
        o0.x = f2lo(acc[i][0]); o0.y = f2hi(acc[i][0]);
        o0.z = f2lo(acc[i][1]); o0.w = f2hi(acc[i][1]);
        o1.x = f2lo(acc[i][2]); o1.y = f2hi(acc[i][2]);
        o1.z = f2lo(acc[i][3]); o1.w = f2hi(acc[i][3]);
        *reinterpret_cast<float4*>(&C[(size_t)m * ldc + n0 + tx * 4]) = o0;
        *reinterpret_cast<float4*>(&C[(size_t)m * ldc + n0 + BN / 2 + tx * 4]) = o1;
    }
}

// ---------------------------------------------------------------------------
// Symmetric fp32 GEMM: C = X.X^T per batch. Lower-triangle tiles only,
// off-diagonal tiles mirror-stored (bit-exact: dot(n,m)==dot(m,n)).
// Grid: (36, 1, B). 128x128 tiles, 256 threads.
// ---------------------------------------------------------------------------
__global__ void __launch_bounds__(256, 2)
gemm_sym(const float* __restrict__ X, int lda, long long sX,
         float* __restrict__ C, int ldc, long long sC, int K)
{
    constexpr int BM = 128, BN = 128, TH = 256, BK = 8;
    constexpr int LA = 2 * BM + 4;
    constexpr int LB = BN + 4;
    constexpr int NX = BN / 8;

    __shared__ float As2[2][BK][LA];
    __shared__ float Bs[2][BK][LB];

    // triangular unrank: t -> (i, j), j <= i
    int t = blockIdx.x;
    int i_ = (int)((sqrtf(8.f * t + 1.f) - 1.f) * 0.5f);
    while ((i_ + 1) * (i_ + 2) / 2 <= t) i_++;
    while (i_ * (i_ + 1) / 2 > t) i_--;
    int j_ = t - i_ * (i_ + 1) / 2;

    const int bz = blockIdx.z;
    const float* A = X + bz * sX;
    float* Cb = C + bz * sC;
    const int m0 = i_ * BM;
    const int n0 = j_ * BN;
    const int tid = threadIdx.x;
    const int tx = tid % NX;
    const int ty = tid / NX;
    const bool a4 = ((lda & 3) == 0);

    unsigned long long acc[8][4];
    #pragma unroll
    for (int i = 0; i < 8; i++)
        #pragma unroll
        for (int j = 0; j < 4; j++) acc[i][j] = 0ull;

    float4 stA[1], stB[1];
    auto ldGA = [&](int k0) {
        int f4 = tid;
        int row = f4 >> 1, kq = (f4 & 1) << 2;
        int k = k0 + kq;
        const float* p = A + (size_t)(m0 + row) * lda;
        float4 v;
        if (a4 && (k + 3) < K) v = *reinterpret_cast<const float4*>(p + k);
        else {
            v.x = (k     < K) ? p[k]     : 0.f;
            v.y = (k + 1 < K) ? p[k + 1] : 0.f;
            v.z = (k + 2 < K) ? p[k + 2] : 0.f;
            v.w = (k + 3 < K) ? p[k + 3] : 0.f;
        }
        stA[0] = v;
    };
    auto ldGB = [&](int k0) {
        int f4 = tid;
        int row = f4 >> 1, kq = (f4 & 1) << 2;
        int k = k0 + kq;
        const float* p = A + (size_t)(n0 + row) * lda;
        float4 v;
        if (a4 && (k + 3) < K) v = *reinterpret_cast<const float4*>(p + k);
        else {
            v.x = (k     < K) ? p[k]     : 0.f;
            v.y = (k + 1 < K) ? p[k + 1] : 0.f;
            v.z = (k + 2 < K) ? p[k + 2] : 0.f;
            v.w = (k + 3 < K) ? p[k + 3] : 0.f;
        }
        stB[0] = v;
    };
    auto stS = [&](int buf) {
        {
            int f4 = tid;
            int row = f4 >> 1, kq = (f4 & 1) << 2;
            float vv[4] = {stA[0].x, stA[0].y, stA[0].z, stA[0].w};
            #pragma unroll
            for (int j = 0; j < 4; j++)
                *reinterpret_cast<float2*>(&As2[buf][kq + j][2 * row]) =
                    make_float2(vv[j], vv[j]);
        }
        {
            int f4 = tid;
            int row = f4 >> 1, kq = (f4 & 1) << 2;
            Bs[buf][kq + 0][row] = stB[0].x;
            Bs[buf][kq + 1][row] = stB[0].y;
            Bs[buf][kq + 2][row] = stB[0].z;
            Bs[buf][kq + 3][row] = stB[0].w;
        }
    };

    const int nt = (K + BK - 1) / BK;
    ldGA(0); ldGB(0); stS(0);
    __syncthreads();

    for (int tt = 0; tt < nt; tt++) {
        int buf = tt & 1;
        if (tt + 1 < nt) { ldGA((tt + 1) * BK); ldGB((tt + 1) * BK); }
        #pragma unroll
        for (int k = 0; k < BK; k++) {
            ulonglong2 a01 = *reinterpret_cast<const ulonglong2*>(&As2[buf][k][2 * (ty * 4)]);
            ulonglong2 a23 = *reinterpret_cast<const ulonglong2*>(&As2[buf][k][2 * (ty * 4) + 4]);
            ulonglong2 a45 = *reinterpret_cast<const ulonglong2*>(&As2[buf][k][2 * (BM / 2 + ty * 4)]);
            ulonglong2 a67 = *reinterpret_cast<const ulonglong2*>(&As2[buf][k][2 * (BM / 2 + ty * 4) + 4]);
            ulonglong2 b01 = *reinterpret_cast<const ulonglong2*>(&Bs[buf][k][tx * 4]);
            ulonglong2 b23 = *reinterpret_cast<const ulonglong2*>(&Bs[buf][k][BN / 2 + tx * 4]);
            unsigned long long av[8] = {a01.x, a01.y, a23.x, a23.y,
                                        a45.x, a45.y, a67.x, a67.y};
            unsigned long long bv[4] = {b01.x, b01.y, b23.x, b23.y};
            #pragma unroll
            for (int i = 0; i < 8; i++)
                #pragma unroll
                for (int j = 0; j < 4; j++)
                    FMA_F32X2(acc[i][j], av[i], bv[j], acc[i][j]);
        }
        if (tt + 1 < nt) stS(buf ^ 1);
        __syncthreads();
    }

    // unpack microtile to 8x8 floats: f[i][q], m_i, n_q
    float f[8][8];
    int mrow[8], ncol[8];
    #pragma unroll
    for (int i = 0; i < 8; i++) {
        mrow[i] = m0 + ((i < 4) ? (ty * 4 + i) : (64 + ty * 4 + i - 4));
        ncol[i] = n0 + ((i < 4) ? (tx * 4 + i) : (64 + tx * 4 + i - 4));
        f[i][0] = f2lo(acc[i][0]); f[i][1] = f2hi(acc[i][0]);
        f[i][2] = f2lo(acc[i][1]); f[i][3] = f2hi(acc[i][1]);
        f[i][4] = f2lo(acc[i][2]); f[i][5] = f2hi(acc[i][2]);
        f[i][6] = f2lo(acc[i][3]); f[i][7] = f2hi(acc[i][3]);
    }

    // normal store C[m, n]
    #pragma unroll
    for (int i = 0; i < 8; i++) {
        *reinterpret_cast<float4*>(&Cb[(size_t)mrow[i] * ldc + ncol[0]]) =
            make_float4(f[i][0], f[i][1], f[i][2], f[i][3]);
        *reinterpret_cast<float4*>(&Cb[(size_t)mrow[i] * ldc + ncol[4]]) =
            make_float4(f[i][4], f[i][5], f[i][6], f[i][7]);
    }
    // mirror store C[n, m] (off-diagonal tiles)
    if (i_ != j_) {
        #pragma unroll
        for (int q = 0; q < 8; q++) {
            *reinterpret_cast<float4*>(&Cb[(size_t)ncol[q] * ldc + mrow[0]]) =
                make_float4(f[0][q], f[1][q], f[2][q], f[3][q]);
            *reinterpret_cast<float4*>(&Cb[(size_t)ncol[q] * ldc + mrow[4]]) =
                make_float4(f[4][q], f[5][q], f[6][q], f[7][q]);
        }
    }
}

// ---------------------------------------------------------------------------
__global__ void xx_kernel(const float* __restrict__ X, int lda, int C, float* __restrict__ xx)
{
    int p = blockIdx.x * 8 + (threadIdx.x >> 5);
    int lane = threadIdx.x & 31;
    const float* r = X + (size_t)p * lda;
    float s = 0.f;
    for (int c = lane; c < C; c += 32) { float v = r[c]; s += v * v; }
    #pragma unroll
    for (int off = 16; off; off >>= 1) s += __shfl_xor_sync(0xffffffffu, s, off);
    if (lane == 0) xx[p] = s;
}

// ---------------------------------------------------------------------------
// top-20: warp per row, full 32-bit key in smem, per-lane top-2 u64 cache.
// Pops via redux.sync.max.u32 (exact, incl. low-index tie-break).
// ---------------------------------------------------------------------------
__device__ __forceinline__ unsigned long long tk_pack(unsigned key, int m) {
    return ((unsigned long long)key << 10) | (unsigned)(1023 - m);
}

__global__ void __launch_bounds__(256)
topk_kernel(const float* __restrict__ inner, const float* __restrict__ xx,
            int* __restrict__ idx_out)
{
    __shared__ unsigned s[8][N_];
    int wid  = threadIdx.x >> 5;
    int lane = threadIdx.x & 31;
    int row  = blockIdx.x * 8 + wid;
    int b    = row >> 10;
    unsigned* sw = s[wid];
    const float* r  = inner + (size_t)row * N_;
    const float* xb = xx + (b << 10);

    unsigned long long e1 = 0, e2 = 0;
    #pragma unroll 8
    for (int i = 0; i < 32; i++) {
        int m = i * 32 + lane;
        float v = 2.f * r[m] - xb[m];
        unsigned u = __float_as_uint(v);
        u = ((int)u < 0) ? ~u : (u | 0x80000000u);
        sw[m] = u;
        unsigned long long enc = tk_pack(u, m);
        if (enc > e1) { e2 = e1; e1 = enc; }
        else if (enc > e2) { e2 = enc; }
    }
    __syncwarp();

    for (int it = 0; it < KNN; it++) {
        unsigned k1 = (unsigned)(e1 >> 10);
        unsigned wkey = redux_max(k1);
        unsigned cand = (k1 == wkey) ? (unsigned)(e1 & 1023u) : 0u;
        unsigned widx = redux_max(cand);
        int m = 1023 - (int)widx;
        if (lane == 0) idx_out[row * KNN + it] = m;
        if (k1 == wkey && (unsigned)(e1 & 1023u) == widx) {
            sw[m] = 0;
            e1 = e2; e2 = 0;
            if (e1 == 0) {
                unsigned long long best = 0;
                #pragma unroll 8
                for (int i = 0; i < 32; i++) {
                    int mm = i * 32 + lane;
                    unsigned vv = sw[mm];
                    if (vv) {
                        unsigned long long enc = tk_pack(vv, mm);
                        best = (enc > best) ? enc : best;
                    }
                }
                e1 = best;
            }
        }
        __syncwarp();
    }
}

// ---------------------------------------------------------------------------
__device__ __forceinline__ void split_store(float v, __nv_bfloat16* h, __nv_bfloat16* l,
                                            size_t i)
{
    __nv_bfloat16 hb = __float2bfloat16(v);
    h[i] = hb;
    l[i] = __float2bfloat16(v - __bfloat162float(hb));
}

__global__ void prep_w(const float* __restrict__ W, int C, int O,
                       const float* __restrict__ bias,
                       const float* __restrict__ bng, const float* __restrict__ bnb,
                       float* __restrict__ utw,
                       __nv_bfloat16* __restrict__ utwh, __nv_bfloat16* __restrict__ utwl,
                       float* __restrict__ tb)
{
    const float inv = 1.0f / sqrtf(1.00001f);
    int i = blockIdx.x * 256 + threadIdx.x;
    if (i < O * C) {
        int o = i / C, c = i - o * C;
        float s = bng[o] * inv;
        float wa = W[o * 2 * C + c];
        float wb = W[o * 2 * C + C + c];
        float vu = s * wa;
        float vt = s * (wb - wa);
        utw[(size_t)o * C + c] = vu;
        utw[(size_t)(O + o) * C + c] = vt;
        split_store(vu, utwh, utwl, (size_t)o * C + c);
        split_store(vt, utwh, utwl, (size_t)(O + o) * C + c);
    }
    if (i < O) {
        float s = bng[i] * inv;
        tb[i] = s * (bias ? bias[i] : 0.f) + bnb[i];
    }
}

__global__ void prep_c5(const float* __restrict__ W,
                        __nv_bfloat16* __restrict__ h, __nv_bfloat16* __restrict__ l)
{
    int i = blockIdx.x * 256 + threadIdx.x;
    if (i < 1024 * 512) split_store(W[i], h, l, i);
}

// ---------------------------------------------------------------------------
__global__ void gathermax(const float* __restrict__ ut, const float* __restrict__ tb,
                          const int* __restrict__ idx,
                          float* __restrict__ xc,
                          __nv_bfloat16* __restrict__ xch, __nv_bfloat16* __restrict__ xcl,
                          int colOff, int CO)
{
    __shared__ int sidx[4][KNN];
    int ty = threadIdx.y, tx = threadIdx.x;
    int p = blockIdx.x * blockDim.y + ty;
    int b = p >> 10;
    if (tx < KNN) sidx[ty][tx] = idx[p * KNN + tx];
    __syncthreads();

    int st = 2 * CO;
    float tv = ut[(size_t)p * st + CO + tx] + tb[tx];
    float m = NEG_INF;
    #pragma unroll 4
    for (int k = 0; k < KNN; k++) {
        int j = sidx[ty][k];
        float v = ut[(size_t)((b << 10) + j) * st + tx] + tv;
        m = fmaxf(m, v);
    }
    m = (m >= 0.f) ? m : 0.01f * m;
    size_t o = (size_t)p * 512 + colOff + tx;
    xc[o] = m;
    split_store(m, xch, xcl, o);
}

// ---------------------------------------------------------------------------
__global__ void zero_pool(unsigned* pool)
{
    int i = blockIdx.x * 256 + threadIdx.x;
    if (i < B_ * 1024) pool[i] = 0u;
}

__global__ void maxpool(const float* __restrict__ e, unsigned* __restrict__ pool)
{
    int o = blockIdx.x * 256 + threadIdx.x;
    int b = blockIdx.y, nz = blockIdx.z;
    const float* base = e + ((size_t)b * 1024 + nz * 64) * 1024 + o;
    float m = NEG_INF;
    #pragma unroll 8
    for (int n = 0; n < 64; n++) m = fmaxf(m, base[(size_t)n * 1024]);
    unsigned uu = __float_as_uint(m);
    uu = (uu >> 31) ? ~uu : (uu | 0x80000000u);
    atomicMax(&pool[b * 1024 + o], uu);
}

__device__ __forceinline__ float dec_pool(unsigned u)
{
    return (u & 0x80000000u) ? __uint_as_float(u & 0x7fffffffu) : __uint_as_float(~u);
}

// ---------------------------------------------------------------------------
__global__ void mlp1(const unsigned* __restrict__ pool, const float* __restrict__ w,
                     const float* __restrict__ g6, const float* __restrict__ b6,
                     float* __restrict__ y1)
{
    int b = blockIdx.y;
    int j = blockIdx.x * 4 + threadIdx.y;
    int lane = threadIdx.x;
    float s = 0.f;
    for (int c = lane; c < 1024; c += 32)
        s += dec_pool(pool[b * 1024 + c]) * w[j * 1024 + c];
    #pragma unroll
    for (int off = 16; off; off >>= 1) s += __shfl_xor_sync(0xffffffffu, s, off);
    if (lane == 0) {
        float v = s * (g6[j] * (1.0f / sqrtf(1.00001f))) + b6[j];
        y1[b * 512 + j] = (v >= 0.f) ? v : 0.01f * v;
    }
}

__global__ void mlp2(const float* __restrict__ y1, const float* __restrict__ w,
                     const float* __restrict__ wb, const float* __restrict__ g7,
                     const float* __restrict__ b7, float* __restrict__ y2)
{
    int b = blockIdx.y;
    int j = blockIdx.x * 4 + threadIdx.y;
    int lane = threadIdx.x;
    float s = 0.f;
    for (int c = lane; c < 512; c += 32) s += y1[b * 512 + c] * w[j * 512 + c];
    #pragma unroll
    for (int off = 16; off; off >>= 1) s += __shfl_xor_sync(0xffffffffu, s, off);
    if (lane == 0) {
        float v = (s + wb[j]) * (g7[j] * (1.0f / sqrtf(1.00001f))) + b7[j];
        y2[b * 256 + j] = (v >= 0.f) ? v : 0.01f * v;
    }
}

__global__ void mlp3(const float* __restrict__ y2, const float* __restrict__ w,
                     const float* __restrict__ wb, float* __restrict__ out)
{
    int b = blockIdx.y;
    int j = blockIdx.x * 4 + threadIdx.y;
    int lane = threadIdx.x;
    float s = 0.f;
    for (int c = lane; c < 256; c += 32) s += y2[b * 256 + c] * w[j * 256 + c];
    #pragma unroll
    for (int off = 16; off; off >>= 1) s += __shfl_xor_sync(0xffffffffu, s, off);
    if (lane == 0) out[b * 40 + j] = s + wb[j];
}

// ---------------------------------------------------------------------------
extern "C" void kernel_launch(void* const* d_in, const int* in_sizes, int n_in,
                              void* d_out, int out_size)
{
    const float* x        = (const float*)d_in[0];
    const float* conv1_w  = (const float*)d_in[1];
    const float* conv1_b  = (const float*)d_in[2];
    const float* bn1_g    = (const float*)d_in[3];
    const float* bn1_b    = (const float*)d_in[4];
    const float* conv2_w  = (const float*)d_in[5];
    const float* bn2_g    = (const float*)d_in[6];
    const float* bn2_b    = (const float*)d_in[7];
    const float* conv3_w  = (const float*)d_in[8];
    const float* bn3_g    = (const float*)d_in[9];
    const float* bn3_b    = (const float*)d_in[10];
    const float* conv4_w  = (const float*)d_in[11];
    const float* bn4_g    = (const float*)d_in[12];
    const float* bn4_b    = (const float*)d_in[13];
    const float* conv5_w  = (const float*)d_in[14];
    const float* lin1_w   = (const float*)d_in[15];
    const float* bn6_g    = (const float*)d_in[16];
    const float* bn6_b    = (const float*)d_in[17];
    const float* lin2_w   = (const float*)d_in[18];
    const float* lin2_b   = (const float*)d_in[19];
    const float* bn7_g    = (const float*)d_in[20];
    const float* bn7_b    = (const float*)d_in[21];
    const float* lin3_w   = (const float*)d_in[22];
    const float* lin3_b   = (const float*)d_in[23];

    float *xc, *inner, *ut, *utw, *tb, *xxp, *y1, *y2;
    __nv_bfloat16 *xch, *xcl, *utwh, *utwl, *c5h, *c5l;
    int* idx; unsigned* pool;
    cudaGetSymbolAddress((void**)&xc,    g_xc);
    cudaGetSymbolAddress((void**)&inner, g_inner);
    cudaGetSymbolAddress((void**)&xch,   g_xch);
    cudaGetSymbolAddress((void**)&xcl,   g_xcl);
    cudaGetSymbolAddress((void**)&ut,    g_ut);
    cudaGetSymbolAddress((void**)&utw,   g_utw);
    cudaGetSymbolAddress((void**)&utwh,  g_utwh);
    cudaGetSymbolAddress((void**)&utwl,  g_utwl);
    cudaGetSymbolAddress((void**)&c5h,   g_c5h);
    cudaGetSymbolAddress((void**)&c5l,   g_c5l);
    cudaGetSymbolAddress((void**)&tb,    g_tb);
    cudaGetSymbolAddress((void**)&xxp,   g_xx);
    cudaGetSymbolAddress((void**)&idx,   g_idx);
    cudaGetSymbolAddress((void**)&pool,  g_pool);
    cudaGetSymbolAddress((void**)&y1,    g_y1);
    cudaGetSymbolAddress((void**)&y2,    g_y2);

    cudaFuncSetAttribute(mma_gemm, cudaFuncAttributeMaxDynamicSharedMemorySize, MMA_SMEM);

    struct Layer {
        int inOff; int Cin; int Cout; int outOff;
        const float* W; const float* bias; const float* g; const float* bb;
    };
    Layer L[4] = {
        { -1,  3,   64,  0,   conv1_w, conv1_b, bn1_g, bn1_b },
        { 0,   64,  64,  64,  conv2_w, nullptr, bn2_g, bn2_b },
        { 64,  64,  128, 128, conv3_w, nullptr, bn3_g, bn3_b },
        { 128, 128, 256, 256, conv4_w, nullptr, bn4_g, bn4_b },
    };

    zero_pool<<<32, 256>>>(pool);

    for (int l = 0; l < 4; l++) {
        const Layer& a = L[l];
        const float* fin = (l == 0) ? x : (xc + a.inOff);
        int lda = (l == 0) ? 3 : 512;

        xx_kernel<<<PTS / 8, 256>>>(fin, lda, a.Cin, xxp);

        // inner[b,n,m] = x_n . x_m — exact fp32, symmetric tiles + mirror
        gemm_sym<<<dim3(36, 1, B_), 256>>>(
            fin, lda, (long long)N_ * lda, inner, N_, (long long)N_ * N_, a.Cin);

        topk_kernel<<<PTS / 8, 256>>>(inner, xxp, idx);

        prep_w<<<(a.Cout * a.Cin + 255) / 256, 256>>>(
            a.W, a.Cin, a.Cout, a.bias, a.g, a.bb, utw, utwh, utwl, tb);

        // combined u|t GEMM: C[p, 0..2Cout)
        if (l == 0) {
            gemm_f2<128, 64, 128><<<dim3(2, PTS / 128, 1), 128>>>(
                x, 3, 0, utw, 3, 0, ut, 128, 0, 3);
        } else {
            mma_gemm<<<dim3(2 * a.Cout / 128, PTS / 128, 1), 256, MMA_SMEM>>>(
                xch + a.inOff, xcl + a.inOff, 512, 0,
                utwh, utwl, a.Cin, 0,
                ut, 2 * a.Cout, 0, a.Cin);
        }

        int ppb = 256 / a.Cout;
        if (ppb < 1) ppb = 1;
        gathermax<<<PTS / ppb, dim3(a.Cout, ppb)>>>(ut, tb, idx, xc, xch, xcl,
                                                    a.outOff, a.Cout);
    }

    // conv5
    prep_c5<<<(1024 * 512 + 255) / 256, 256>>>(conv5_w, c5h, c5l);
    mma_gemm<<<dim3(8, PTS / 128, 1), 256, MMA_SMEM>>>(
        xch, xcl, 512, 0, c5h, c5l, 512, 0, inner, 1024, 0, 512);

    maxpool<<<dim3(4, B_, 16), 256>>>(inner, pool);

    mlp1<<<dim3(128, B_), dim3(32, 4)>>>(pool, lin1_w, bn6_g, bn6_b, y1);
    mlp2<<<dim3(64, B_),  dim3(32, 4)>>>(y1, lin2_w, lin2_b, bn7_g, bn7_b, y2);
    mlp3<<<dim3(10, B_),  dim3(32, 4)>>>(y2, lin3_w, lin3_b, (float*)d_out);
}

// round 8
// speedup vs baseline: 1.9464x; 1.2019x over previous
#include <cuda_runtime.h>
#include <cuda_bf16.h>
#include <cstdint>

// DGCNN forward.
//   edge_conv:  out[b,n,o] = lrelu( max_k ( u[b,idx_k,o] + t[b,n,o] ) )
//   u = (s*W_a)@x ; t = (s*(W_b-W_a))@x + (s*bias + bn_b)
// KNN inner GEMMs: exact fp32 SIMT, symmetric (lower triangle + mirror store).
// u|t GEMMs (l2-l4) + conv5: bf16-split x3 mma.sync (continuous paths).

#define B_   8
#define N_   1024
#define PTS  (B_ * N_)
#define KNN  20
#define NEG_INF __int_as_float(0xff800000)

__device__ static float          g_xc[PTS * 512];
__device__ static __nv_bfloat16  g_xch[PTS * 512];
__device__ static __nv_bfloat16  g_xcl[PTS * 512];
__device__ static float          g_inner[PTS * 1024];
__device__ static float          g_ut[PTS * 512];
__device__ static float          g_utw[512 * 128];
__device__ static __nv_bfloat16  g_utwh[512 * 128];
__device__ static __nv_bfloat16  g_utwl[512 * 128];
__device__ static __nv_bfloat16  g_c5h[1024 * 512];
__device__ static __nv_bfloat16  g_c5l[1024 * 512];
__device__ static float          g_tb[256];
__device__ static float          g_xx[PTS];
__device__ static int            g_idx[PTS * KNN];
__device__ static unsigned       g_pool[B_ * 1024];
__device__ static float          g_y1[B_ * 512];
__device__ static float          g_y2[B_ * 256];

__device__ __forceinline__ uint32_t smem_u32(const void* p) {
    uint32_t a;
    asm("{ .reg .u64 t; cvta.to.shared.u64 t, %1; cvt.u32.u64 %0, t; }"
        : "=r"(a) : "l"(p));
    return a;
}

__device__ __forceinline__ unsigned redux_max(unsigned v) {
    unsigned r;
    asm("redux.sync.max.u32 %0, %1, 0xffffffff;" : "=r"(r) : "r"(v));
    return r;
}

#define LDSM_X4(r0, r1, r2, r3, addr) \
    asm volatile("ldmatrix.sync.aligned.m8n8.x4.shared.b16 {%0,%1,%2,%3}, [%4];" \
                 : "=r"(r0), "=r"(r1), "=r"(r2), "=r"(r3) : "r"(addr))

#define MMA_BF16(c, a, b0, b1) \
    asm volatile( \
        "mma.sync.aligned.m16n8k16.row.col.f32.bf16.bf16.f32 " \
        "{%0,%1,%2,%3}, {%4,%5,%6,%7}, {%8,%9}, {%0,%1,%2,%3};" \
        : "+f"((c)[0]), "+f"((c)[1]), "+f"((c)[2]), "+f"((c)[3]) \
        : "r"((a)[0]), "r"((a)[1]), "r"((a)[2]), "r"((a)[3]), \
          "r"(b0), "r"(b1))

// ---------------------------------------------------------------------------
// bf16-split mma.sync GEMM (continuous paths only).
// ---------------------------------------------------------------------------
#define SKA       40
#define TILE_B    (128 * SKA * 2)
#define STAGE_B   (4 * TILE_B)
#define MMA_SMEM  (2 * STAGE_B)

__global__ void __launch_bounds__(256)
mma_gemm(const __nv_bfloat16* __restrict__ Ah, const __nv_bfloat16* __restrict__ Al,
         int lda, long long sA,
         const __nv_bfloat16* __restrict__ Bh, const __nv_bfloat16* __restrict__ Bl,
         int ldb, long long sB,
         float* __restrict__ C, int ldc, long long sC, int K)
{
    extern __shared__ char smem[];
    const uint32_t sb0 = smem_u32(smem);

    const int tid  = threadIdx.x;
    const int wid  = tid >> 5;
    const int lane = tid & 31;
    const int bz = blockIdx.z;
    Ah += bz * sA; Al += bz * sA; Bh += bz * sB; Bl += bz * sB;
    const int m0 = blockIdx.y * 128;
    const int n0 = blockIdx.x * 128;
    const int m_warp = (wid & 1) * 64;
    const int n_warp = (wid >> 1) * 32;

    float acc[4][4][4];
    #pragma unroll
    for (int i = 0; i < 4; i++)
        #pragma unroll
        for (int j = 0; j < 4; j++)
            #pragma unroll
            for (int q = 0; q < 4; q++) acc[i][j][q] = 0.f;

    uint4 stg[8];
    auto ldG = [&](int kc) {
        #pragma unroll
        for (int i = 0; i < 8; i++) {
            int u = tid + i * 256;
            int tile = u >> 9;
            int r = (u >> 2) & 127;
            int q = u & 3;
            const __nv_bfloat16* src;
            int ld_, r0;
            if (tile == 0)      { src = Ah; ld_ = lda; r0 = m0; }
            else if (tile == 1) { src = Al; ld_ = lda; r0 = m0; }
            else if (tile == 2) { src = Bh; ld_ = ldb; r0 = n0; }
            else                { src = Bl; ld_ = ldb; r0 = n0; }
            stg[i] = *reinterpret_cast<const uint4*>(
                src + (size_t)(r0 + r) * ld_ + kc + q * 8);
        }
    };
    auto stS = [&](int stage) {
        char* base = smem + stage * STAGE_B;
        #pragma unroll
        for (int i = 0; i < 8; i++) {
            int u = tid + i * 256;
            int tile = u >> 9;
            int r = (u >> 2) & 127;
            int q = u & 3;
            *reinterpret_cast<uint4*>(base + tile * TILE_B + r * (SKA * 2) + q * 16) = stg[i];
        }
    };

    const int nc = K >> 5;
    ldG(0); stS(0);
    __syncthreads();

    for (int c = 0; c < nc; c++) {
        int buf = c & 1;
        if (c + 1 < nc) ldG((c + 1) * 32);

        const uint32_t sb = sb0 + buf * STAGE_B;
        #pragma unroll
        for (int ks = 0; ks < 32; ks += 16) {
            uint32_t ah[4][4], al[4][4], bh[2][4], bl[2][4];
            const uint32_t lrow = (lane & 15);
            const uint32_t lcol = (lane >> 4) * 8;
            #pragma unroll
            for (int mt = 0; mt < 4; mt++) {
                uint32_t off = ((m_warp + mt * 16 + lrow) * SKA + ks + lcol) * 2;
                LDSM_X4(ah[mt][0], ah[mt][1], ah[mt][2], ah[mt][3], sb + off);
                LDSM_X4(al[mt][0], al[mt][1], al[mt][2], al[mt][3], sb + TILE_B + off);
            }
            #pragma unroll
            for (int np = 0; np < 2; np++) {
                uint32_t off = ((n_warp + np * 16 + lrow) * SKA + ks + lcol) * 2;
                LDSM_X4(bh[np][0], bh[np][1], bh[np][2], bh[np][3], sb + 2 * TILE_B + off);
                LDSM_X4(bl[np][0], bl[np][1], bl[np][2], bl[np][3], sb + 3 * TILE_B + off);
            }
            #pragma unroll
            for (int mt = 0; mt < 4; mt++)
                #pragma unroll
                for (int nt = 0; nt < 4; nt++) {
                    int np = nt >> 1, half = nt & 1;
                    MMA_BF16(acc[mt][nt], ah[mt], bh[np][half], bh[np][2 + half]);
                    MMA_BF16(acc[mt][nt], ah[mt], bl[np][half], bl[np][2 + half]);
                    MMA_BF16(acc[mt][nt], al[mt], bh[np][half], bh[np][2 + half]);
                }
        }

        if (c + 1 < nc) stS(buf ^ 1);
        __syncthreads();
    }

    #pragma unroll
    for (int mt = 0; mt < 4; mt++)
        #pragma unroll
        for (int nt = 0; nt < 4; nt++) {
            int rm = m0 + m_warp + mt * 16 + (lane >> 2);
            int cn = n0 + n_warp + nt * 8 + (lane & 3) * 2;
            *reinterpret_cast<float2*>(&C[(size_t)rm * ldc + cn]) =
                make_float2(acc[mt][nt][0], acc[mt][nt][1]);
            *reinterpret_cast<float2*>(&C[(size_t)(rm + 8) * ldc + cn]) =
                make_float2(acc[mt][nt][2], acc[mt][nt][3]);
        }
}

// ---------------------------------------------------------------------------
// fp32 SIMT GEMM machinery (exact path)
// ---------------------------------------------------------------------------
#define FMA_F32X2(d, a, b, c) \
    asm("fma.rn.f32x2 %0, %1, %2, %3;" : "=l"(d) : "l"(a), "l"(b), "l"(c))
__device__ __forceinline__ float f2lo(unsigned long long v) {
    return __uint_as_float((unsigned)(v & 0xffffffffull));
}
__device__ __forceinline__ float f2hi(unsigned long long v) {
    return __uint_as_float((unsigned)(v >> 32));
}

template<int BM, int BN, int TH>
__global__ void __launch_bounds__(TH, 2)
gemm_f2(const float* __restrict__ A, int lda, long long sA,
        const float* __restrict__ B, int ldb, long long sB,
        float* __restrict__ C, int ldc, long long sC, int K)
{
    constexpr int BK = 8;
    constexpr int LA = 2 * BM + 4;
    constexpr int LB = BN + 4;
    constexpr int NX = BN / 8;
    constexpr int NY = BM / 8;
    static_assert(NX * NY == TH, "threads");
    constexpr int CA = (BM * 2) / TH;
    constexpr int CB = (BN * 2) / TH;

    __shared__ float As2[2][BK][LA];
    __shared__ float Bs[2][BK][LB];

    const int bz = blockIdx.z;
    A += bz * sA; B += bz * sB; C += bz * sC;
    const int m0 = blockIdx.y * BM;
    const int n0 = blockIdx.x * BN;
    const int tid = threadIdx.x;
    const int tx = tid % NX;
    const int ty = tid / NX;
    const bool a4 = ((lda & 3) == 0);
    const bool b4 = ((ldb & 3) == 0);

    unsigned long long acc[8][4];
    #pragma unroll
    for (int i = 0; i < 8; i++)
        #pragma unroll
        for (int j = 0; j < 4; j++) acc[i][j] = 0ull;

    float4 stA[CA], stB[CB];
    auto ldGA = [&](int k0) {
        #pragma unroll
        for (int i = 0; i < CA; i++) {
            int f4 = tid + i * TH;
            int row = f4 >> 1, kq = (f4 & 1) << 2;
            int k = k0 + kq;
            const float* p = A + (size_t)(m0 + row) * lda;
            float4 v;
            if (a4 && (k + 3) < K) v = *reinterpret_cast<const float4*>(p + k);
            else {
                v.x = (k     < K) ? p[k]     : 0.f;
                v.y = (k + 1 < K) ? p[k + 1] : 0.f;
                v.z = (k + 2 < K) ? p[k + 2] : 0.f;
                v.w = (k + 3 < K) ? p[k + 3] : 0.f;
            }
            stA[i] = v;
        }
    };
    auto ldGB = [&](int k0) {
        #pragma unroll
        for (int i = 0; i < CB; i++) {
            int f4 = tid + i * TH;
            int row = f4 >> 1, kq = (f4 & 1) << 2;
            int k = k0 + kq;
            const float* p = B + (size_t)(n0 + row) * ldb;
            float4 v;
            if (b4 && (k + 3) < K) v = *reinterpret_cast<const float4*>(p + k);
            else {
                v.x = (k     < K) ? p[k]     : 0.f;
                v.y = (k + 1 < K) ? p[k + 1] : 0.f;
                v.z = (k + 2 < K) ? p[k + 2] : 0.f;
                v.w = (k + 3 < K) ? p[k + 3] : 0.f;
            }
            stB[i] = v;
        }
    };
    auto stS = [&](int buf) {
        #pragma unroll
        for (int i = 0; i < CA; i++) {
            int f4 = tid + i * TH;
            int row = f4 >> 1, kq = (f4 & 1) << 2;
            float vv[4] = {stA[i].x, stA[i].y, stA[i].z, stA[i].w};
            #pragma unroll
            for (int j = 0; j < 4; j++)
                *reinterpret_cast<float2*>(&As2[buf][kq + j][2 * row]) =
                    make_float2(vv[j], vv[j]);
        }
        #pragma unroll
        for (int i = 0; i < CB; i++) {
            int f4 = tid + i * TH;
            int row = f4 >> 1, kq = (f4 & 1) << 2;
            Bs[buf][kq + 0][row] = stB[i].x;
            Bs[buf][kq + 1][row] = stB[i].y;
            Bs[buf][kq + 2][row] = stB[i].z;
            Bs[buf][kq + 3][row] = stB[i].w;
        }
    };

    const int nt = (K + BK - 1) / BK;
    ldGA(0); ldGB(0); stS(0);
    __syncthreads();

    for (int t = 0; t < nt; t++) {
        int buf = t & 1;
        if (t + 1 < nt) { ldGA((t + 1) * BK); ldGB((t + 1) * BK); }
        #pragma unroll
        for (int k = 0; k < BK; k++) {
            ulonglong2 a01 = *reinterpret_cast<const ulonglong2*>(&As2[buf][k][2 * (ty * 4)]);
            ulonglong2 a23 = *reinterpret_cast<const ulonglong2*>(&As2[buf][k][2 * (ty * 4) + 4]);
            ulonglong2 a45 = *reinterpret_cast<const ulonglong2*>(&As2[buf][k][2 * (BM / 2 + ty * 4)]);
            ulonglong2 a67 = *reinterpret_cast<const ulonglong2*>(&As2[buf][k][2 * (BM / 2 + ty * 4) + 4]);
            ulonglong2 b01 = *reinterpret_cast<const ulonglong2*>(&Bs[buf][k][tx * 4]);
            ulonglong2 b23 = *reinterpret_cast<const ulonglong2*>(&Bs[buf][k][BN / 2 + tx * 4]);
            unsigned long long av[8] = {a01.x, a01.y, a23.x, a23.y,
                                        a45.x, a45.y, a67.x, a67.y};
            unsigned long long bv[4] = {b01.x, b01.y, b23.x, b23.y};
            #pragma unroll
            for (int i = 0; i < 8; i++)
                #pragma unroll
                for (int j = 0; j < 4; j++)
                    FMA_F32X2(acc[i][j], av[i], bv[j], acc[i][j]);
        }
        if (t + 1 < nt) stS(buf ^ 1);
        __syncthreads();
    }

    #pragma unroll
    for (int i = 0; i < 8; i++) {
        int m = m0 + ((i < 4) ? (ty * 4 + i) : (BM / 2 + ty * 4 + i - 4));
        float4 o0, o1;
        o0.x = f2lo(acc[i][0]); o0.y = f2hi(acc[i][0]);
        o0.z = f2lo(acc[i][1]); o0.w = f2hi(acc[i][1]);
        o1.x = f2lo(acc[i][2]); o1.y = f2hi(acc[i][2]);
        o1.z = f2lo(acc[i][3]); o1.w = f2hi(acc[i][3]);
        *reinterpret_cast<float4*>(&C[(size_t)m * ldc + n0 + tx * 4]) = o0;
        *reinterpret_cast<float4*>(&C[(size_t)m * ldc + n0 + BN / 2 + tx * 4]) = o1;
    }
}

// ---------------------------------------------------------------------------
// Symmetric fp32 GEMM: C = X.X^T per batch (lower triangle + mirror store).
// ---------------------------------------------------------------------------
__global__ void __launch_bounds__(256, 2)
gemm_sym(const float* __restrict__ X, int lda, long long sX,
         float* __restrict__ C, int ldc, long long sC, int K)
{
    constexpr int BM = 128, BN = 128, BK = 8;
    constexpr int LA = 2 * BM + 4;
    constexpr int LB = BN + 4;
    constexpr int NX = BN / 8;

    __shared__ float As2[2][BK][LA];
    __shared__ float Bs[2][BK][LB];

    int t = blockIdx.x;
    int i_ = (int)((sqrtf(8.f * t + 1.f) - 1.f) * 0.5f);
    while ((i_ + 1) * (i_ + 2) / 2 <= t) i_++;
    while (i_ * (i_ + 1) / 2 > t) i_--;
    int j_ = t - i_ * (i_ + 1) / 2;

    const int bz = blockIdx.z;
    const float* A = X + bz * sX;
    float* Cb = C + bz * sC;
    const int m0 = i_ * BM;
    const int n0 = j_ * BN;
    const int tid = threadIdx.x;
    const int tx = tid % NX;
    const int ty = tid / NX;
    const bool a4 = ((lda & 3) == 0);

    unsigned long long acc[8][4];
    #pragma unroll
    for (int i = 0; i < 8; i++)
        #pragma unroll
        for (int j = 0; j < 4; j++) acc[i][j] = 0ull;

    float4 stA[1], stB[1];
    auto ldGA = [&](int k0) {
        int row = tid >> 1, kq = (tid & 1) << 2;
        int k = k0 + kq;
        const float* p = A + (size_t)(m0 + row) * lda;
        float4 v;
        if (a4 && (k + 3) < K) v = *reinterpret_cast<const float4*>(p + k);
        else {
            v.x = (k     < K) ? p[k]     : 0.f;
            v.y = (k + 1 < K) ? p[k + 1] : 0.f;
            v.z = (k + 2 < K) ? p[k + 2] : 0.f;
            v.w = (k + 3 < K) ? p[k + 3] : 0.f;
        }
        stA[0] = v;
    };
    auto ldGB = [&](int k0) {
        int row = tid >> 1, kq = (tid & 1) << 2;
        int k = k0 + kq;
        const float* p = A + (size_t)(n0 + row) * lda;
        float4 v;
        if (a4 && (k + 3) < K) v = *reinterpret_cast<const float4*>(p + k);
        else {
            v.x = (k     < K) ? p[k]     : 0.f;
            v.y = (k + 1 < K) ? p[k + 1] : 0.f;
            v.z = (k + 2 < K) ? p[k + 2] : 0.f;
            v.w = (k + 3 < K) ? p[k + 3] : 0.f;
        }
        stB[0] = v;
    };
    auto stS = [&](int buf) {
        int row = tid >> 1, kq = (tid & 1) << 2;
        float vv[4] = {stA[0].x, stA[0].y, stA[0].z, stA[0].w};
        #pragma unroll
        for (int j = 0; j < 4; j++)
            *reinterpret_cast<float2*>(&As2[buf][kq + j][2 * row]) =
                make_float2(vv[j], vv[j]);
        Bs[buf][kq + 0][row] = stB[0].x;
        Bs[buf][kq + 1][row] = stB[0].y;
        Bs[buf][kq + 2][row] = stB[0].z;
        Bs[buf][kq + 3][row] = stB[0].w;
    };

    const int nt = (K + BK - 1) / BK;
    ldGA(0); ldGB(0); stS(0);
    __syncthreads();

    for (int tt = 0; tt < nt; tt++) {
        int buf = tt & 1;
        if (tt + 1 < nt) { ldGA((tt + 1) * BK); ldGB((tt + 1) * BK); }
        #pragma unroll
        for (int k = 0; k < BK; k++) {
            ulonglong2 a01 = *reinterpret_cast<const ulonglong2*>(&As2[buf][k][2 * (ty * 4)]);
            ulonglong2 a23 = *reinterpret_cast<const ulonglong2*>(&As2[buf][k][2 * (ty * 4) + 4]);
            ulonglong2 a45 = *reinterpret_cast<const ulonglong2*>(&As2[buf][k][2 * (BM / 2 + ty * 4)]);
            ulonglong2 a67 = *reinterpret_cast<const ulonglong2*>(&As2[buf][k][2 * (BM / 2 + ty * 4) + 4]);
            ulonglong2 b01 = *reinterpret_cast<const ulonglong2*>(&Bs[buf][k][tx * 4]);
            ulonglong2 b23 = *reinterpret_cast<const ulonglong2*>(&Bs[buf][k][BN / 2 + tx * 4]);
            unsigned long long av[8] = {a01.x, a01.y, a23.x, a23.y,
                                        a45.x, a45.y, a67.x, a67.y};
            unsigned long long bv[4] = {b01.x, b01.y, b23.x, b23.y};
            #pragma unroll
            for (int i = 0; i < 8; i++)
                #pragma unroll
                for (int j = 0; j < 4; j++)
                    FMA_F32X2(acc[i][j], av[i], bv[j], acc[i][j]);
        }
        if (tt + 1 < nt) stS(buf ^ 1);
        __syncthreads();
    }

    float f[8][8];
    int mrow[8], ncol[8];
    #pragma unroll
    for (int i = 0; i < 8; i++) {
        mrow[i] = m0 + ((i < 4) ? (ty * 4 + i) : (64 + ty * 4 + i - 4));
        ncol[i] = n0 + ((i < 4) ? (tx * 4 + i) : (64 + tx * 4 + i - 4));
        f[i][0] = f2lo(acc[i][0]); f[i][1] = f2hi(acc[i][0]);
        f[i][2] = f2lo(acc[i][1]); f[i][3] = f2hi(acc[i][1]);
        f[i][4] = f2lo(acc[i][2]); f[i][5] = f2hi(acc[i][2]);
        f[i][6] = f2lo(acc[i][3]); f[i][7] = f2hi(acc[i][3]);
    }

    #pragma unroll
    for (int i = 0; i < 8; i++) {
        *reinterpret_cast<float4*>(&Cb[(size_t)mrow[i] * ldc + ncol[0]]) =
            make_float4(f[i][0], f[i][1], f[i][2], f[i][3]);
        *reinterpret_cast<float4*>(&Cb[(size_t)mrow[i] * ldc + ncol[4]]) =
            make_float4(f[i][4], f[i][5], f[i][6], f[i][7]);
    }
    if (i_ != j_) {
        #pragma unroll
        for (int q = 0; q < 8; q++) {
            *reinterpret_cast<float4*>(&Cb[(size_t)ncol[q] * ldc + mrow[0]]) =
                make_float4(f[0][q], f[1][q], f[2][q], f[3][q]);
            *reinterpret_cast<float4*>(&Cb[(size_t)ncol[q] * ldc + mrow[4]]) =
                make_float4(f[4][q], f[5][q], f[6][q], f[7][q]);
        }
    }
}

// ---------------------------------------------------------------------------
// xx from the inner-product diagonal (computed by gemm_sym).
// ---------------------------------------------------------------------------
__global__ void diag_xx(const float* __restrict__ inner, float* __restrict__ xx)
{
    int p = blockIdx.x * 256 + threadIdx.x;
    if (p < PTS) xx[p] = inner[(size_t)p * N_ + (p & (N_ - 1))];
}

// ---------------------------------------------------------------------------
// top-20: warp per row. Vectorized scan (float4), u32 key top-2 cache with
// index registers (strict > + ascending m = exact low-index tie-break),
// pops via redux.sync.max.u32 pair.
// ---------------------------------------------------------------------------
__device__ __forceinline__ unsigned fenc(float v) {
    unsigned u = __float_as_uint(v);
    return u ^ (((unsigned)((int)u >> 31)) | 0x80000000u);
}
__device__ __forceinline__ void tk_upd(unsigned& k1, unsigned& m1,
                                       unsigned& k2, unsigned& m2,
                                       unsigned e, unsigned m) {
    if (e > k1)      { k2 = k1; m2 = m1; k1 = e; m1 = m; }
    else if (e > k2) { k2 = e; m2 = m; }
}

__global__ void __launch_bounds__(256)
topk_kernel(const float* __restrict__ inner, const float* __restrict__ xx,
            int* __restrict__ idx_out)
{
    __shared__ uint4 s4[8][N_ / 4];
    int wid  = threadIdx.x >> 5;
    int lane = threadIdx.x & 31;
    int row  = blockIdx.x * 8 + wid;
    int b    = row >> 10;
    uint4* sw4 = s4[wid];
    unsigned* sw = reinterpret_cast<unsigned*>(sw4);
    const float4* r4 = reinterpret_cast<const float4*>(inner + (size_t)row * N_);
    const float4* x4 = reinterpret_cast<const float4*>(xx + (b << 10));

    unsigned k1 = 0, m1 = 0, k2 = 0, m2 = 0;
    #pragma unroll
    for (int i = 0; i < 8; i++) {
        int q = i * 32 + lane;
        float4 rv = r4[q];
        float4 xv = x4[q];
        unsigned mb = (unsigned)q * 4;
        unsigned e0 = fenc(fmaf(2.f, rv.x, -xv.x));
        unsigned e1 = fenc(fmaf(2.f, rv.y, -xv.y));
        unsigned e2 = fenc(fmaf(2.f, rv.z, -xv.z));
        unsigned e3 = fenc(fmaf(2.f, rv.w, -xv.w));
        sw4[q] = make_uint4(e0, e1, e2, e3);
        tk_upd(k1, m1, k2, m2, e0, mb);
        tk_upd(k1, m1, k2, m2, e1, mb + 1);
        tk_upd(k1, m1, k2, m2, e2, mb + 2);
        tk_upd(k1, m1, k2, m2, e3, mb + 3);
    }
    __syncwarp();

    for (int it = 0; it < KNN; it++) {
        unsigned wkey = redux_max(k1);
        unsigned cand = (k1 == wkey) ? (1023u - m1) : 0u;
        unsigned widx = redux_max(cand);
        unsigned m = 1023u - widx;
        if (lane == 0) idx_out[row * KNN + it] = (int)m;
        if (k1 == wkey && (1023u - m1) == widx) {
            sw[m] = 0;
            k1 = k2; m1 = m2; k2 = 0; m2 = 0;
            if (k1 == 0) {
                #pragma unroll
                for (int i = 0; i < 8; i++) {
                    int q = i * 32 + lane;
                    uint4 v = sw4[q];
                    unsigned mb = (unsigned)q * 4;
                    tk_upd(k1, m1, k2, m2, v.x, mb);
                    tk_upd(k1, m1, k2, m2, v.y, mb + 1);
                    tk_upd(k1, m1, k2, m2, v.z, mb + 2);
                    tk_upd(k1, m1, k2, m2, v.w, mb + 3);
                }
            }
        }
        __syncwarp();
    }
}

// ---------------------------------------------------------------------------
__device__ __forceinline__ void split_store(float v, __nv_bfloat16* h, __nv_bfloat16* l,
                                            size_t i)
{
    __nv_bfloat16 hb = __float2bfloat16(v);
    h[i] = hb;
    l[i] = __float2bfloat16(v - __bfloat162float(hb));
}

__global__ void prep_w(const float* __restrict__ W, int C, int O,
                       const float* __restrict__ bias,
                       const float* __restrict__ bng, const float* __restrict__ bnb,
                       float* __restrict__ utw,
                       __nv_bfloat16* __restrict__ utwh, __nv_bfloat16* __restrict__ utwl,
                       float* __restrict__ tb)
{
    const float inv = 1.0f / sqrtf(1.00001f);
    int i = blockIdx.x * 256 + threadIdx.x;
    if (i < O * C) {
        int o = i / C, c = i - o * C;
        float s = bng[o] * inv;
        float wa = W[o * 2 * C + c];
        float wb = W[o * 2 * C + C + c];
        float vu = s * wa;
        float vt = s * (wb - wa);
        utw[(size_t)o * C + c] = vu;
        utw[(size_t)(O + o) * C + c] = vt;
        split_store(vu, utwh, utwl, (size_t)o * C + c);
        split_store(vt, utwh, utwl, (size_t)(O + o) * C + c);
    }
    if (i < O) {
        float s = bng[i] * inv;
        tb[i] = s * (bias ? bias[i] : 0.f) + bnb[i];
    }
}

__global__ void prep_c5(const float* __restrict__ W,
                        __nv_bfloat16* __restrict__ h, __nv_bfloat16* __restrict__ l)
{
    int i = blockIdx.x * 256 + threadIdx.x;
    if (i < 1024 * 512) split_store(W[i], h, l, i);
}

// ---------------------------------------------------------------------------
// gather + max + lrelu (vectorized: thread handles 4 channels).
// blockDim = (CO/4, ppb). ut layout: [p][2*CO]: [0,CO)=u, [CO,2CO)=t.
// ---------------------------------------------------------------------------
__global__ void gathermax(const float* __restrict__ ut, const float* __restrict__ tb,
                          const int* __restrict__ idx,
                          float* __restrict__ xc,
                          __nv_bfloat16* __restrict__ xch, __nv_bfloat16* __restrict__ xcl,
                          int colOff, int CO)
{
    __shared__ int sidx[16][KNN];
    int ty = threadIdx.y, tx = threadIdx.x;
    int p = blockIdx.x * blockDim.y + ty;
    int b = p >> 10;
    for (int k = tx; k < KNN; k += blockDim.x) sidx[ty][k] = idx[p * KNN + k];
    __syncthreads();

    int st = 2 * CO;
    float4 tv = *reinterpret_cast<const float4*>(ut + (size_t)p * st + CO + tx * 4);
    float4 bv = *reinterpret_cast<const float4*>(tb + tx * 4);
    tv.x += bv.x; tv.y += bv.y; tv.z += bv.z; tv.w += bv.w;

    float4 mx = make_float4(NEG_INF, NEG_INF, NEG_INF, NEG_INF);
    #pragma unroll 4
    for (int k = 0; k < KNN; k++) {
        int j = sidx[ty][k];
        float4 v = *reinterpret_cast<const float4*>(
            ut + (size_t)((b << 10) + j) * st + tx * 4);
        mx.x = fmaxf(mx.x, v.x + tv.x);
        mx.y = fmaxf(mx.y, v.y + tv.y);
        mx.z = fmaxf(mx.z, v.z + tv.z);
        mx.w = fmaxf(mx.w, v.w + tv.w);
    }
    mx.x = (mx.x >= 0.f) ? mx.x : 0.01f * mx.x;
    mx.y = (mx.y >= 0.f) ? mx.y : 0.01f * mx.y;
    mx.z = (mx.z >= 0.f) ? mx.z : 0.01f * mx.z;
    mx.w = (mx.w >= 0.f) ? mx.w : 0.01f * mx.w;

    size_t o = (size_t)p * 512 + colOff + tx * 4;
    *reinterpret_cast<float4*>(xc + o) = mx;

    float vals[4] = {mx.x, mx.y, mx.z, mx.w};
    __nv_bfloat16 hb[4], lb[4];
    #pragma unroll
    for (int i = 0; i < 4; i++) {
        hb[i] = __float2bfloat16(vals[i]);
        lb[i] = __float2bfloat16(vals[i] - __bfloat162float(hb[i]));
    }
    *reinterpret_cast<uint2*>(xch + o) = *reinterpret_cast<uint2*>(hb);
    *reinterpret_cast<uint2*>(xcl + o) = *reinterpret_cast<uint2*>(lb);
}

// ---------------------------------------------------------------------------
__global__ void zero_pool(unsigned* pool)
{
    int i = blockIdx.x * 256 + threadIdx.x;
    if (i < B_ * 1024) pool[i] = 0u;
}

__global__ void maxpool(const float* __restrict__ e, unsigned* __restrict__ pool)
{
    int o = blockIdx.x * 256 + threadIdx.x;
    int b = blockIdx.y, nz = blockIdx.z;
    const float* base = e + ((size_t)b * 1024 + nz * 64) * 1024 + o;
    float m = NEG_INF;
    #pragma unroll 8
    for (int n = 0; n < 64; n++) m = fmaxf(m, base[(size_t)n * 1024]);
    unsigned uu = __float_as_uint(m);
    uu = (uu >> 31) ? ~uu : (uu | 0x80000000u);
    atomicMax(&pool[b * 1024 + o], uu);
}

__device__ __forceinline__ float dec_pool(unsigned u)
{
    return (u & 0x80000000u) ? __uint_as_float(u & 0x7fffffffu) : __uint_as_float(~u);
}

// ---------------------------------------------------------------------------
__global__ void mlp1(const unsigned* __restrict__ pool, const float* __restrict__ w,
                     const float* __restrict__ g6, const float* __restrict__ b6,
                     float* __restrict__ y1)
{
    int b = blockIdx.y;
    int j = blockIdx.x * 4 + threadIdx.y;
    int lane = threadIdx.x;
    float s = 0.f;
    for (int c = lane; c < 1024; c += 32)
        s += dec_pool(pool[b * 1024 + c]) * w[j * 1024 + c];
    #pragma unroll
    for (int off = 16; off; off >>= 1) s += __shfl_xor_sync(0xffffffffu, s, off);
    if (lane == 0) {
        float v = s * (g6[j] * (1.0f / sqrtf(1.00001f))) + b6[j];
        y1[b * 512 + j] = (v >= 0.f) ? v : 0.01f * v;
    }
}

__global__ void mlp2(const float* __restrict__ y1, const float* __restrict__ w,
                     const float* __restrict__ wb, const float* __restrict__ g7,
                     const float* __restrict__ b7, float* __restrict__ y2)
{
    int b = blockIdx.y;
    int j = blockIdx.x * 4 + threadIdx.y;
    int lane = threadIdx.x;
    float s = 0.f;
    for (int c = lane; c < 512; c += 32) s += y1[b * 512 + c] * w[j * 512 + c];
    #pragma unroll
    for (int off = 16; off; off >>= 1) s += __shfl_xor_sync(0xffffffffu, s, off);
    if (lane == 0) {
        float v = (s + wb[j]) * (g7[j] * (1.0f / sqrtf(1.00001f))) + b7[j];
        y2[b * 256 + j] = (v >= 0.f) ? v : 0.01f * v;
    }
}

__global__ void mlp3(const float* __restrict__ y2, const float* __restrict__ w,
                     const float* __restrict__ wb, float* __restrict__ out)
{
    int b = blockIdx.y;
    int j = blockIdx.x * 4 + threadIdx.y;
    int lane = threadIdx.x;
    float s = 0.f;
    for (int c = lane; c < 256; c += 32) s += y2[b * 256 + c] * w[j * 256 + c];
    #pragma unroll
    for (int off = 16; off; off >>= 1) s += __shfl_xor_sync(0xffffffffu, s, off);
    if (lane == 0) out[b * 40 + j] = s + wb[j];
}

// ---------------------------------------------------------------------------
extern "C" void kernel_launch(void* const* d_in, const int* in_sizes, int n_in,
                              void* d_out, int out_size)
{
    const float* x        = (const float*)d_in[0];
    const float* conv1_w  = (const float*)d_in[1];
    const float* conv1_b  = (const float*)d_in[2];
    const float* bn1_g    = (const float*)d_in[3];
    const float* bn1_b    = (const float*)d_in[4];
    const float* conv2_w  = (const float*)d_in[5];
    const float* bn2_g    = (const float*)d_in[6];
    const float* bn2_b    = (const float*)d_in[7];
    const float* conv3_w  = (const float*)d_in[8];
    const float* bn3_g    = (const float*)d_in[9];
    const float* bn3_b    = (const float*)d_in[10];
    const float* conv4_w  = (const float*)d_in[11];
    const float* bn4_g    = (const float*)d_in[12];
    const float* bn4_b    = (const float*)d_in[13];
    const float* conv5_w  = (const float*)d_in[14];
    const float* lin1_w   = (const float*)d_in[15];
    const float* bn6_g    = (const float*)d_in[16];
    const float* bn6_b    = (const float*)d_in[17];
    const float* lin2_w   = (const float*)d_in[18];
    const float* lin2_b   = (const float*)d_in[19];
    const float* bn7_g    = (const float*)d_in[20];
    const float* bn7_b    = (const float*)d_in[21];
    const float* lin3_w   = (const float*)d_in[22];
    const float* lin3_b   = (const float*)d_in[23];

    float *xc, *inner, *ut, *utw, *tb, *xxp, *y1, *y2;
    __nv_bfloat16 *xch, *xcl, *utwh, *utwl, *c5h, *c5l;
    int* idx; unsigned* pool;
    cudaGetSymbolAddress((void**)&xc,    g_xc);
    cudaGetSymbolAddress((void**)&inner, g_inner);
    cudaGetSymbolAddress((void**)&xch,   g_xch);
    cudaGetSymbolAddress((void**)&xcl,   g_xcl);
    cudaGetSymbolAddress((void**)&ut,    g_ut);
    cudaGetSymbolAddress((void**)&utw,   g_utw);
    cudaGetSymbolAddress((void**)&utwh,  g_utwh);
    cudaGetSymbolAddress((void**)&utwl,  g_utwl);
    cudaGetSymbolAddress((void**)&c5h,   g_c5h);
    cudaGetSymbolAddress((void**)&c5l,   g_c5l);
    cudaGetSymbolAddress((void**)&tb,    g_tb);
    cudaGetSymbolAddress((void**)&xxp,   g_xx);
    cudaGetSymbolAddress((void**)&idx,   g_idx);
    cudaGetSymbolAddress((void**)&pool,  g_pool);
    cudaGetSymbolAddress((void**)&y1,    g_y1);
    cudaGetSymbolAddress((void**)&y2,    g_y2);

    cudaFuncSetAttribute(mma_gemm, cudaFuncAttributeMaxDynamicSharedMemorySize, MMA_SMEM);

    struct Layer {
        int inOff; int Cin; int Cout; int outOff;
        const float* W; const float* bias; const float* g; const float* bb;
    };
    Layer L[4] = {
        { -1,  3,   64,  0,   conv1_w, conv1_b, bn1_g, bn1_b },
        { 0,   64,  64,  64,  conv2_w, nullptr, bn2_g, bn2_b },
        { 64,  64,  128, 128, conv3_w, nullptr, bn3_g, bn3_b },
        { 128, 128, 256, 256, conv4_w, nullptr, bn4_g, bn4_b },
    };

    zero_pool<<<32, 256>>>(pool);

    for (int l = 0; l < 4; l++) {
        const Layer& a = L[l];
        const float* fin = (l == 0) ? x : (xc + a.inOff);
        int lda = (l == 0) ? 3 : 512;

        // inner[b,n,m] = x_n . x_m — exact fp32, symmetric tiles + mirror
        gemm_sym<<<dim3(36, 1, B_), 256>>>(
            fin, lda, (long long)N_ * lda, inner, N_, (long long)N_ * N_, a.Cin);

        // xx from diagonal
        diag_xx<<<32, 256>>>(inner, xxp);

        topk_kernel<<<PTS / 8, 256>>>(inner, xxp, idx);

        prep_w<<<(a.Cout * a.Cin + 255) / 256, 256>>>(
            a.W, a.Cin, a.Cout, a.bias, a.g, a.bb, utw, utwh, utwl, tb);

        // combined u|t GEMM: C[p, 0..2Cout)
        if (l == 0) {
            gemm_f2<128, 64, 128><<<dim3(2, PTS / 128, 1), 128>>>(
                x, 3, 0, utw, 3, 0, ut, 128, 0, 3);
        } else {
            mma_gemm<<<dim3(2 * a.Cout / 128, PTS / 128, 1), 256, MMA_SMEM>>>(
                xch + a.inOff, xcl + a.inOff, 512, 0,
                utwh, utwl, a.Cin, 0,
                ut, 2 * a.Cout, 0, a.Cin);
        }

        int cx = a.Cout / 4;            // threads over channels (float4)
        int ppb = 1024 / a.Cout;        // points per block (cx*ppb = 256)
        if (ppb > 16) ppb = 16;
        gathermax<<<PTS / ppb, dim3(cx, ppb)>>>(ut, tb, idx, xc, xch, xcl,
                                                a.outOff, a.Cout);
    }

    // conv5
    prep_c5<<<(1024 * 512 + 255) / 256, 256>>>(conv5_w, c5h, c5l);
    mma_gemm<<<dim3(8, PTS / 128, 1), 256, MMA_SMEM>>>(
        xch, xcl, 512, 0, c5h, c5l, 512, 0, inner, 1024, 0, 512);

    maxpool<<<dim3(4, B_, 16), 256>>>(inner, pool);

    mlp1<<<dim3(128, B_), dim3(32, 4)>>>(pool, lin1_w, bn6_g, bn6_b, y1);
    mlp2<<<dim3(64, B_),  dim3(32, 4)>>>(y1, lin2_w, lin2_b, bn7_g, bn7_b, y2);
    mlp3<<<dim3(10, B_),  dim3(32, 4)>>>(y2, lin3_w, lin3_b, (float*)d_out);
}

// round 9
// speedup vs baseline: 2.0675x; 1.0622x over previous
#include <cuda_runtime.h>
#include <cuda_bf16.h>
#include <cstdint>

// DGCNN forward.
//   edge_conv:  out[b,n,o] = lrelu( max_k ( u[b,idx_k,o] + t[b,n,o] ) )
//   u = (s*W_a)@x ; t = (s*(W_b-W_a))@x + (s*bias + bn_b)
// KNN inner GEMMs: exact fp32 SIMT, symmetric (lower triangle + mirror store).
// u|t GEMMs (l2-l4): bf16-split x3 mma.sync. conv5: same, fused with max-pool.
// Second stream overlaps [prep_w -> ut GEMM] with [gemm_sym -> topk].

#define B_   8
#define N_   1024
#define PTS  (B_ * N_)
#define KNN  20
#define NEG_INF __int_as_float(0xff800000)

__device__ static float          g_xc[PTS * 512];
__device__ static __nv_bfloat16  g_xch[PTS * 512];
__device__ static __nv_bfloat16  g_xcl[PTS * 512];
__device__ static float          g_inner[PTS * 1024];
__device__ static float          g_ut[PTS * 512];
__device__ static float          g_utw[512 * 128];
__device__ static __nv_bfloat16  g_utwh[512 * 128];
__device__ static __nv_bfloat16  g_utwl[512 * 128];
__device__ static __nv_bfloat16  g_c5h[1024 * 512];
__device__ static __nv_bfloat16  g_c5l[1024 * 512];
__device__ static float          g_tb[256];
__device__ static float          g_xx[PTS];
__device__ static int            g_idx[PTS * KNN];
__device__ static unsigned       g_pool[B_ * 1024];
__device__ static float          g_y1[B_ * 512];
__device__ static float          g_y2[B_ * 256];

__device__ __forceinline__ uint32_t smem_u32(const void* p) {
    uint32_t a;
    asm("{ .reg .u64 t; cvta.to.shared.u64 t, %1; cvt.u32.u64 %0, t; }"
        : "=r"(a) : "l"(p));
    return a;
}

__device__ __forceinline__ unsigned redux_max(unsigned v) {
    unsigned r;
    asm("redux.sync.max.u32 %0, %1, 0xffffffff;" : "=r"(r) : "r"(v));
    return r;
}

#define LDSM_X4(r0, r1, r2, r3, addr) \
    asm volatile("ldmatrix.sync.aligned.m8n8.x4.shared.b16 {%0,%1,%2,%3}, [%4];" \
                 : "=r"(r0), "=r"(r1), "=r"(r2), "=r"(r3) : "r"(addr))

#define MMA_BF16(c, a, b0, b1) \
    asm volatile( \
        "mma.sync.aligned.m16n8k16.row.col.f32.bf16.bf16.f32 " \
        "{%0,%1,%2,%3}, {%4,%5,%6,%7}, {%8,%9}, {%0,%1,%2,%3};" \
        : "+f"((c)[0]), "+f"((c)[1]), "+f"((c)[2]), "+f"((c)[3]) \
        : "r"((a)[0]), "r"((a)[1]), "r"((a)[2]), "r"((a)[3]), \
          "r"(b0), "r"(b1))

// ---------------------------------------------------------------------------
// bf16-split mma.sync GEMM mainloop (shared between C-store and pool variants)
// ---------------------------------------------------------------------------
#define SKA       40
#define TILE_B    (128 * SKA * 2)
#define STAGE_B   (4 * TILE_B)
#define MMA_SMEM  (2 * STAGE_B)
#define MMA_SMEM_POOL (2 * STAGE_B + 512)

struct MmaCtx {
    float acc[4][4][4];
    int m_warp, n_warp, lane;
};

__device__ __forceinline__ void mma_mainloop(
    char* smem, uint32_t sb0, MmaCtx& cx,
    const __nv_bfloat16* Ah, const __nv_bfloat16* Al, int lda, int m0,
    const __nv_bfloat16* Bh, const __nv_bfloat16* Bl, int ldb, int n0, int K)
{
    const int tid  = threadIdx.x;
    const int wid  = tid >> 5;
    const int lane = tid & 31;
    cx.lane = lane;
    cx.m_warp = (wid & 1) * 64;
    cx.n_warp = (wid >> 1) * 32;

    #pragma unroll
    for (int i = 0; i < 4; i++)
        #pragma unroll
        for (int j = 0; j < 4; j++)
            #pragma unroll
            for (int q = 0; q < 4; q++) cx.acc[i][j][q] = 0.f;

    uint4 stg[8];
    auto ldG = [&](int kc) {
        #pragma unroll
        for (int i = 0; i < 8; i++) {
            int u = tid + i * 256;
            int tile = u >> 9;
            int r = (u >> 2) & 127;
            int q = u & 3;
            const __nv_bfloat16* src;
            int ld_, r0;
            if (tile == 0)      { src = Ah; ld_ = lda; r0 = m0; }
            else if (tile == 1) { src = Al; ld_ = lda; r0 = m0; }
            else if (tile == 2) { src = Bh; ld_ = ldb; r0 = n0; }
            else                { src = Bl; ld_ = ldb; r0 = n0; }
            stg[i] = *reinterpret_cast<const uint4*>(
                src + (size_t)(r0 + r) * ld_ + kc + q * 8);
        }
    };
    auto stS = [&](int stage) {
        char* base = smem + stage * STAGE_B;
        #pragma unroll
        for (int i = 0; i < 8; i++) {
            int u = tid + i * 256;
            int tile = u >> 9;
            int r = (u >> 2) & 127;
            int q = u & 3;
            *reinterpret_cast<uint4*>(base + tile * TILE_B + r * (SKA * 2) + q * 16) = stg[i];
        }
    };

    const int nc = K >> 5;
    ldG(0); stS(0);
    __syncthreads();

    for (int c = 0; c < nc; c++) {
        int buf = c & 1;
        if (c + 1 < nc) ldG((c + 1) * 32);

        const uint32_t sb = sb0 + buf * STAGE_B;
        #pragma unroll
        for (int ks = 0; ks < 32; ks += 16) {
            uint32_t ah[4][4], al[4][4], bh[2][4], bl[2][4];
            const uint32_t lrow = (lane & 15);
            const uint32_t lcol = (lane >> 4) * 8;
            #pragma unroll
            for (int mt = 0; mt < 4; mt++) {
                uint32_t off = ((cx.m_warp + mt * 16 + lrow) * SKA + ks + lcol) * 2;
                LDSM_X4(ah[mt][0], ah[mt][1], ah[mt][2], ah[mt][3], sb + off);
                LDSM_X4(al[mt][0], al[mt][1], al[mt][2], al[mt][3], sb + TILE_B + off);
            }
            #pragma unroll
            for (int np = 0; np < 2; np++) {
                uint32_t off = ((cx.n_warp + np * 16 + lrow) * SKA + ks + lcol) * 2;
                LDSM_X4(bh[np][0], bh[np][1], bh[np][2], bh[np][3], sb + 2 * TILE_B + off);
                LDSM_X4(bl[np][0], bl[np][1], bl[np][2], bl[np][3], sb + 3 * TILE_B + off);
            }
            #pragma unroll
            for (int mt = 0; mt < 4; mt++)
                #pragma unroll
                for (int nt = 0; nt < 4; nt++) {
                    int np = nt >> 1, half = nt & 1;
                    MMA_BF16(cx.acc[mt][nt], ah[mt], bh[np][half], bh[np][2 + half]);
                    MMA_BF16(cx.acc[mt][nt], ah[mt], bl[np][half], bl[np][2 + half]);
                    MMA_BF16(cx.acc[mt][nt], al[mt], bh[np][half], bh[np][2 + half]);
                }
        }

        if (c + 1 < nc) stS(buf ^ 1);
        __syncthreads();
    }
}

__global__ void __launch_bounds__(256)
mma_gemm(const __nv_bfloat16* __restrict__ Ah, const __nv_bfloat16* __restrict__ Al,
         int lda, long long sA,
         const __nv_bfloat16* __restrict__ Bh, const __nv_bfloat16* __restrict__ Bl,
         int ldb, long long sB,
         float* __restrict__ C, int ldc, long long sC, int K)
{
    extern __shared__ char smem[];
    const uint32_t sb0 = smem_u32(smem);
    const int bz = blockIdx.z;
    Ah += bz * sA; Al += bz * sA; Bh += bz * sB; Bl += bz * sB; C += bz * sC;
    const int m0 = blockIdx.y * 128;
    const int n0 = blockIdx.x * 128;

    MmaCtx cx;
    mma_mainloop(smem, sb0, cx, Ah, Al, lda, m0, Bh, Bl, ldb, n0, K);

    #pragma unroll
    for (int mt = 0; mt < 4; mt++)
        #pragma unroll
        for (int nt = 0; nt < 4; nt++) {
            int rm = m0 + cx.m_warp + mt * 16 + (cx.lane >> 2);
            int cn = n0 + cx.n_warp + nt * 8 + (cx.lane & 3) * 2;
            *reinterpret_cast<float2*>(&C[(size_t)rm * ldc + cn]) =
                make_float2(cx.acc[mt][nt][0], cx.acc[mt][nt][1]);
            *reinterpret_cast<float2*>(&C[(size_t)(rm + 8) * ldc + cn]) =
                make_float2(cx.acc[mt][nt][2], cx.acc[mt][nt][3]);
        }
}

// conv5 variant: no C store; reduce max over the tile's 128 rows and
// atomicMax into the global pool (monotonic uint encoding).
__global__ void __launch_bounds__(256)
mma_gemm_pool(const __nv_bfloat16* __restrict__ Ah, const __nv_bfloat16* __restrict__ Al,
              int lda,
              const __nv_bfloat16* __restrict__ Bh, const __nv_bfloat16* __restrict__ Bl,
              int ldb,
              unsigned* __restrict__ pool, int K)
{
    extern __shared__ char smem[];
    const uint32_t sb0 = smem_u32(smem);
    unsigned* spool = reinterpret_cast<unsigned*>(smem + 2 * STAGE_B);
    const int tid = threadIdx.x;
    if (tid < 128) spool[tid] = 0u;

    const int m0 = blockIdx.y * 128;
    const int n0 = blockIdx.x * 128;
    const int b  = m0 >> 10;

    MmaCtx cx;
    mma_mainloop(smem, sb0, cx, Ah, Al, lda, m0, Bh, Bl, ldb, n0, K);

    #pragma unroll
    for (int nt = 0; nt < 4; nt++)
        #pragma unroll
        for (int j = 0; j < 2; j++) {
            float v = NEG_INF;
            #pragma unroll
            for (int mt = 0; mt < 4; mt++)
                v = fmaxf(v, fmaxf(cx.acc[mt][nt][j], cx.acc[mt][nt][2 + j]));
            v = fmaxf(v, __shfl_xor_sync(0xffffffffu, v, 4));
            v = fmaxf(v, __shfl_xor_sync(0xffffffffu, v, 8));
            v = fmaxf(v, __shfl_xor_sync(0xffffffffu, v, 16));
            if ((cx.lane >> 2) == 0) {
                unsigned uu = __float_as_uint(v);
                uu = (uu >> 31) ? ~uu : (uu | 0x80000000u);
                atomicMax(&spool[cx.n_warp + nt * 8 + (cx.lane & 3) * 2 + j], uu);
            }
        }
    __syncthreads();
    if (tid < 128) atomicMax(&pool[b * 1024 + n0 + tid], spool[tid]);
}

// ---------------------------------------------------------------------------
// fp32 SIMT GEMM machinery (exact path)
// ---------------------------------------------------------------------------
#define FMA_F32X2(d, a, b, c) \
    asm("fma.rn.f32x2 %0, %1, %2, %3;" : "=l"(d) : "l"(a), "l"(b), "l"(c))
__device__ __forceinline__ float f2lo(unsigned long long v) {
    return __uint_as_float((unsigned)(v & 0xffffffffull));
}
__device__ __forceinline__ float f2hi(unsigned long long v) {
    return __uint_as_float((unsigned)(v >> 32));
}

template<int BM, int BN, int TH>
__global__ void __launch_bounds__(TH, 2)
gemm_f2(const float* __restrict__ A, int lda, long long sA,
        const float* __restrict__ B, int ldb, long long sB,
        float* __restrict__ C, int ldc, long long sC, int K)
{
    constexpr int BK = 8;
    constexpr int LA = 2 * BM + 4;
    constexpr int LB = BN + 4;
    constexpr int NX = BN / 8;
    constexpr int NY = BM / 8;
    static_assert(NX * NY == TH, "threads");
    constexpr int CA = (BM * 2) / TH;
    constexpr int CB = (BN * 2) / TH;

    __shared__ float As2[2][BK][LA];
    __shared__ float Bs[2][BK][LB];

    const int bz = blockIdx.z;
    A += bz * sA; B += bz * sB; C += bz * sC;
    const int m0 = blockIdx.y * BM;
    const int n0 = blockIdx.x * BN;
    const int tid = threadIdx.x;
    const int tx = tid % NX;
    const int ty = tid / NX;
    const bool a4 = ((lda & 3) == 0);
    const bool b4 = ((ldb & 3) == 0);

    unsigned long long acc[8][4];
    #pragma unroll
    for (int i = 0; i < 8; i++)
        #pragma unroll
        for (int j = 0; j < 4; j++) acc[i][j] = 0ull;

    float4 stA[CA], stB[CB];
    auto ldGA = [&](int k0) {
        #pragma unroll
        for (int i = 0; i < CA; i++) {
            int f4 = tid + i * TH;
            int row = f4 >> 1, kq = (f4 & 1) << 2;
            int k = k0 + kq;
            const float* p = A + (size_t)(m0 + row) * lda;
            float4 v;
            if (a4 && (k + 3) < K) v = *reinterpret_cast<const float4*>(p + k);
            else {
                v.x = (k     < K) ? p[k]     : 0.f;
                v.y = (k + 1 < K) ? p[k + 1] : 0.f;
                v.z = (k + 2 < K) ? p[k + 2] : 0.f;
                v.w = (k + 3 < K) ? p[k + 3] : 0.f;
            }
            stA[i] = v;
        }
    };
    auto ldGB = [&](int k0) {
        #pragma unroll
        for (int i = 0; i < CB; i++) {
            int f4 = tid + i * TH;
            int row = f4 >> 1, kq = (f4 & 1) << 2;
            int k = k0 + kq;
            const float* p = B + (size_t)(n0 + row) * ldb;
            float4 v;
            if (b4 && (k + 3) < K) v = *reinterpret_cast<const float4*>(p + k);
            else {
                v.x = (k     < K) ? p[k]     : 0.f;
                v.y = (k + 1 < K) ? p[k + 1] : 0.f;
                v.z = (k + 2 < K) ? p[k + 2] : 0.f;
                v.w = (k + 3 < K) ? p[k + 3] : 0.f;
            }
            stB[i] = v;
        }
    };
    auto stS = [&](int buf) {
        #pragma unroll
        for (int i = 0; i < CA; i++) {
            int f4 = tid + i * TH;
            int row = f4 >> 1, kq = (f4 & 1) << 2;
            float vv[4] = {stA[i].x, stA[i].y, stA[i].z, stA[i].w};
            #pragma unroll
            for (int j = 0; j < 4; j++)
                *reinterpret_cast<float2*>(&As2[buf][kq + j][2 * row]) =
                    make_float2(vv[j], vv[j]);
        }
        #pragma unroll
        for (int i = 0; i < CB; i++) {
            int f4 = tid + i * TH;
            int row = f4 >> 1, kq = (f4 & 1) << 2;
            Bs[buf][kq + 0][row] = stB[i].x;
            Bs[buf][kq + 1][row] = stB[i].y;
            Bs[buf][kq + 2][row] = stB[i].z;
            Bs[buf][kq + 3][row] = stB[i].w;
        }
    };

    const int nt = (K + BK - 1) / BK;
    ldGA(0); ldGB(0); stS(0);
    __syncthreads();

    for (int t = 0; t < nt; t++) {
        int buf = t & 1;
        if (t + 1 < nt) { ldGA((t + 1) * BK); ldGB((t + 1) * BK); }
        #pragma unroll
        for (int k = 0; k < BK; k++) {
            ulonglong2 a01 = *reinterpret_cast<const ulonglong2*>(&As2[buf][k][2 * (ty * 4)]);
            ulonglong2 a23 = *reinterpret_cast<const ulonglong2*>(&As2[buf][k][2 * (ty * 4) + 4]);
            ulonglong2 a45 = *reinterpret_cast<const ulonglong2*>(&As2[buf][k][2 * (BM / 2 + ty * 4)]);
            ulonglong2 a67 = *reinterpret_cast<const ulonglong2*>(&As2[buf][k][2 * (BM / 2 + ty * 4) + 4]);
            ulonglong2 b01 = *reinterpret_cast<const ulonglong2*>(&Bs[buf][k][tx * 4]);
            ulonglong2 b23 = *reinterpret_cast<const ulonglong2*>(&Bs[buf][k][BN / 2 + tx * 4]);
            unsigned long long av[8] = {a01.x, a01.y, a23.x, a23.y,
                                        a45.x, a45.y, a67.x, a67.y};
            unsigned long long bv[4] = {b01.x, b01.y, b23.x, b23.y};
            #pragma unroll
            for (int i = 0; i < 8; i++)
                #pragma unroll
                for (int j = 0; j < 4; j++)
                    FMA_F32X2(acc[i][j], av[i], bv[j], acc[i][j]);
        }
        if (t + 1 < nt) stS(buf ^ 1);
        __syncthreads();
    }

    #pragma unroll
    for (int i = 0; i < 8; i++) {
        int m = m0 + ((i < 4) ? (ty * 4 + i) : (BM / 2 + ty * 4 + i - 4));
        float4 o0, o1;
        o0.x = f2lo(acc[i][0]); o0.y = f2hi(acc[i][0]);
        o0.z = f2lo(acc[i][1]); o0.w = f2hi(acc[i][1]);
        o1.x = f2lo(acc[i][2]); o1.y = f2hi(acc[i][2]);
        o1.z = f2lo(acc[i][3]); o1.w = f2hi(acc[i][3]);
        *reinterpret_cast<float4*>(&C[(size_t)m * ldc + n0 + tx * 4]) = o0;
        *reinterpret_cast<float4*>(&C[(size_t)m * ldc + n0 + BN / 2 + tx * 4]) = o1;
    }
}

// ---------------------------------------------------------------------------
// Symmetric fp32 GEMM: C = X.X^T per batch (lower triangle + mirror store).
// ---------------------------------------------------------------------------
__global__ void __launch_bounds__(256, 2)
gemm_sym(const float* __restrict__ X, int lda, long long sX,
         float* __restrict__ C, int ldc, long long sC, int K)
{
    constexpr int BM = 128, BN = 128, BK = 8;
    constexpr int LA = 2 * BM + 4;
    constexpr int LB = BN + 4;
    constexpr int NX = BN / 8;

    __shared__ float As2[2][BK][LA];
    __shared__ float Bs[2][BK][LB];

    int t = blockIdx.x;
    int i_ = (int)((sqrtf(8.f * t + 1.f) - 1.f) * 0.5f);
    while ((i_ + 1) * (i_ + 2) / 2 <= t) i_++;
    while (i_ * (i_ + 1) / 2 > t) i_--;
    int j_ = t - i_ * (i_ + 1) / 2;

    const int bz = blockIdx.z;
    const float* A = X + bz * sX;
    float* Cb = C + bz * sC;
    const int m0 = i_ * BM;
    const int n0 = j_ * BN;
    const int tid = threadIdx.x;
    const int tx = tid % NX;
    const int ty = tid / NX;
    const bool a4 = ((lda & 3) == 0);

    unsigned long long acc[8][4];
    #pragma unroll
    for (int i = 0; i < 8; i++)
        #pragma unroll
        for (int j = 0; j < 4; j++) acc[i][j] = 0ull;

    float4 stA[1], stB[1];
    auto ldGA = [&](int k0) {
        int row = tid >> 1, kq = (tid & 1) << 2;
        int k = k0 + kq;
        const float* p = A + (size_t)(m0 + row) * lda;
        float4 v;
        if (a4 && (k + 3) < K) v = *reinterpret_cast<const float4*>(p + k);
        else {
            v.x = (k     < K) ? p[k]     : 0.f;
            v.y = (k + 1 < K) ? p[k + 1] : 0.f;
            v.z = (k + 2 < K) ? p[k + 2] : 0.f;
            v.w = (k + 3 < K) ? p[k + 3] : 0.f;
        }
        stA[0] = v;
    };
    auto ldGB = [&](int k0) {
        int row = tid >> 1, kq = (tid & 1) << 2;
        int k = k0 + kq;
        const float* p = A + (size_t)(n0 + row) * lda;
        float4 v;
        if (a4 && (k + 3) < K) v = *reinterpret_cast<const float4*>(p + k);
        else {
            v.x = (k     < K) ? p[k]     : 0.f;
            v.y = (k + 1 < K) ? p[k + 1] : 0.f;
            v.z = (k + 2 < K) ? p[k + 2] : 0.f;
            v.w = (k + 3 < K) ? p[k + 3] : 0.f;
        }
        stB[0] = v;
    };
    auto stS = [&](int buf) {
        int row = tid >> 1, kq = (tid & 1) << 2;
        float vv[4] = {stA[0].x, stA[0].y, stA[0].z, stA[0].w};
        #pragma unroll
        for (int j = 0; j < 4; j++)
            *reinterpret_cast<float2*>(&As2[buf][kq + j][2 * row]) =
                make_float2(vv[j], vv[j]);
        Bs[buf][kq + 0][row] = stB[0].x;
        Bs[buf][kq + 1][row] = stB[0].y;
        Bs[buf][kq + 2][row] = stB[0].z;
        Bs[buf][kq + 3][row] = stB[0].w;
    };

    const int nt = (K + BK - 1) / BK;
    ldGA(0); ldGB(0); stS(0);
    __syncthreads();

    for (int tt = 0; tt < nt; tt++) {
        int buf = tt & 1;
        if (tt + 1 < nt) { ldGA((tt + 1) * BK); ldGB((tt + 1) * BK); }
        #pragma unroll
        for (int k = 0; k < BK; k++) {
            ulonglong2 a01 = *reinterpret_cast<const ulonglong2*>(&As2[buf][k][2 * (ty * 4)]);
            ulonglong2 a23 = *reinterpret_cast<const ulonglong2*>(&As2[buf][k][2 * (ty * 4) + 4]);
            ulonglong2 a45 = *reinterpret_cast<const ulonglong2*>(&As2[buf][k][2 * (BM / 2 + ty * 4)]);
            ulonglong2 a67 = *reinterpret_cast<const ulonglong2*>(&As2[buf][k][2 * (BM / 2 + ty * 4) + 4]);
            ulonglong2 b01 = *reinterpret_cast<const ulonglong2*>(&Bs[buf][k][tx * 4]);
            ulonglong2 b23 = *reinterpret_cast<const ulonglong2*>(&Bs[buf][k][BN / 2 + tx * 4]);
            unsigned long long av[8] = {a01.x, a01.y, a23.x, a23.y,
                                        a45.x, a45.y, a67.x, a67.y};
            unsigned long long bv[4] = {b01.x, b01.y, b23.x, b23.y};
            #pragma unroll
            for (int i = 0; i < 8; i++)
                #pragma unroll
                for (int j = 0; j < 4; j++)
                    FMA_F32X2(acc[i][j], av[i], bv[j], acc[i][j]);
        }
        if (tt + 1 < nt) stS(buf ^ 1);
        __syncthreads();
    }

    float f[8][8];
    int mrow[8], ncol[8];
    #pragma unroll
    for (int i = 0; i < 8; i++) {
        mrow[i] = m0 + ((i < 4) ? (ty * 4 + i) : (64 + ty * 4 + i - 4));
        ncol[i] = n0 + ((i < 4) ? (tx * 4 + i) : (64 + tx * 4 + i - 4));
        f[i][0] = f2lo(acc[i][0]); f[i][1] = f2hi(acc[i][0]);
        f[i][2] = f2lo(acc[i][1]); f[i][3] = f2hi(acc[i][1]);
        f[i][4] = f2lo(acc[i][2]); f[i][5] = f2hi(acc[i][2]);
        f[i][6] = f2lo(acc[i][3]); f[i][7] = f2hi(acc[i][3]);
    }

    #pragma unroll
    for (int i = 0; i < 8; i++) {
        *reinterpret_cast<float4*>(&Cb[(size_t)mrow[i] * ldc + ncol[0]]) =
            make_float4(f[i][0], f[i][1], f[i][2], f[i][3]);
        *reinterpret_cast<float4*>(&Cb[(size_t)mrow[i] * ldc + ncol[4]]) =
            make_float4(f[i][4], f[i][5], f[i][6], f[i][7]);
    }
    if (i_ != j_) {
        #pragma unroll
        for (int q = 0; q < 8; q++) {
            *reinterpret_cast<float4*>(&Cb[(size_t)ncol[q] * ldc + mrow[0]]) =
                make_float4(f[0][q], f[1][q], f[2][q], f[3][q]);
            *reinterpret_cast<float4*>(&Cb[(size_t)ncol[q] * ldc + mrow[4]]) =
                make_float4(f[4][q], f[5][q], f[6][q], f[7][q]);
        }
    }
}

// ---------------------------------------------------------------------------
__global__ void diag_xx(const float* __restrict__ inner, float* __restrict__ xx)
{
    int p = blockIdx.x * 256 + threadIdx.x;
    if (p < PTS) xx[p] = inner[(size_t)p * N_ + (p & (N_ - 1))];
}

// ---------------------------------------------------------------------------
// top-20: warp per row. Vectorized scan, u32 key top-2 cache + index regs,
// pops via redux.sync.max.u32 pair.
// ---------------------------------------------------------------------------
__device__ __forceinline__ unsigned fenc(float v) {
    unsigned u = __float_as_uint(v);
    return u ^ (((unsigned)((int)u >> 31)) | 0x80000000u);
}
__device__ __forceinline__ void tk_upd(unsigned& k1, unsigned& m1,
                                       unsigned& k2, unsigned& m2,
                                       unsigned e, unsigned m) {
    if (e > k1)      { k2 = k1; m2 = m1; k1 = e; m1 = m; }
    else if (e > k2) { k2 = e; m2 = m; }
}

__global__ void __launch_bounds__(256)
topk_kernel(const float* __restrict__ inner, const float* __restrict__ xx,
            int* __restrict__ idx_out)
{
    __shared__ uint4 s4[8][N_ / 4];
    int wid  = threadIdx.x >> 5;
    int lane = threadIdx.x & 31;
    int row  = blockIdx.x * 8 + wid;
    int b    = row >> 10;
    uint4* sw4 = s4[wid];
    unsigned* sw = reinterpret_cast<unsigned*>(sw4);
    const float4* r4 = reinterpret_cast<const float4*>(inner + (size_t)row * N_);
    const float4* x4 = reinterpret_cast<const float4*>(xx + (b << 10));

    unsigned k1 = 0, m1 = 0, k2 = 0, m2 = 0;
    #pragma unroll
    for (int i = 0; i < 8; i++) {
        int q = i * 32 + lane;
        float4 rv = r4[q];
        float4 xv = x4[q];
        unsigned mb = (unsigned)q * 4;
        unsigned e0 = fenc(fmaf(2.f, rv.x, -xv.x));
        unsigned e1 = fenc(fmaf(2.f, rv.y, -xv.y));
        unsigned e2 = fenc(fmaf(2.f, rv.z, -xv.z));
        unsigned e3 = fenc(fmaf(2.f, rv.w, -xv.w));
        sw4[q] = make_uint4(e0, e1, e2, e3);
        tk_upd(k1, m1, k2, m2, e0, mb);
        tk_upd(k1, m1, k2, m2, e1, mb + 1);
        tk_upd(k1, m1, k2, m2, e2, mb + 2);
        tk_upd(k1, m1, k2, m2, e3, mb + 3);
    }
    __syncwarp();

    for (int it = 0; it < KNN; it++) {
        unsigned wkey = redux_max(k1);
        unsigned cand = (k1 == wkey) ? (1023u - m1) : 0u;
        unsigned widx = redux_max(cand);
        unsigned m = 1023u - widx;
        if (lane == 0) idx_out[row * KNN + it] = (int)m;
        if (k1 == wkey && (1023u - m1) == widx) {
            sw[m] = 0;
            k1 = k2; m1 = m2; k2 = 0; m2 = 0;
            if (k1 == 0) {
                #pragma unroll
                for (int i = 0; i < 8; i++) {
                    int q = i * 32 + lane;
                    uint4 v = sw4[q];
                    unsigned mb = (unsigned)q * 4;
                    tk_upd(k1, m1, k2, m2, v.x, mb);
                    tk_upd(k1, m1, k2, m2, v.y, mb + 1);
                    tk_upd(k1, m1, k2, m2, v.z, mb + 2);
                    tk_upd(k1, m1, k2, m2, v.w, mb + 3);
                }
            }
        }
        __syncwarp();
    }
}

// ---------------------------------------------------------------------------
__device__ __forceinline__ void split_store(float v, __nv_bfloat16* h, __nv_bfloat16* l,
                                            size_t i)
{
    __nv_bfloat16 hb = __float2bfloat16(v);
    h[i] = hb;
    l[i] = __float2bfloat16(v - __bfloat162float(hb));
}

__global__ void prep_w(const float* __restrict__ W, int C, int O,
                       const float* __restrict__ bias,
                       const float* __restrict__ bng, const float* __restrict__ bnb,
                       float* __restrict__ utw,
                       __nv_bfloat16* __restrict__ utwh, __nv_bfloat16* __restrict__ utwl,
                       float* __restrict__ tb)
{
    const float inv = 1.0f / sqrtf(1.00001f);
    int i = blockIdx.x * 256 + threadIdx.x;
    if (i < O * C) {
        int o = i / C, c = i - o * C;
        float s = bng[o] * inv;
        float wa = W[o * 2 * C + c];
        float wb = W[o * 2 * C + C + c];
        float vu = s * wa;
        float vt = s * (wb - wa);
        utw[(size_t)o * C + c] = vu;
        utw[(size_t)(O + o) * C + c] = vt;
        split_store(vu, utwh, utwl, (size_t)o * C + c);
        split_store(vt, utwh, utwl, (size_t)(O + o) * C + c);
    }
    if (i < O) {
        float s = bng[i] * inv;
        tb[i] = s * (bias ? bias[i] : 0.f) + bnb[i];
    }
}

__global__ void prep_c5(const float* __restrict__ W,
                        __nv_bfloat16* __restrict__ h, __nv_bfloat16* __restrict__ l)
{
    int i = blockIdx.x * 256 + threadIdx.x;
    if (i < 1024 * 512) split_store(W[i], h, l, i);
}

// ---------------------------------------------------------------------------
__global__ void gathermax(const float* __restrict__ ut, const float* __restrict__ tb,
                          const int* __restrict__ idx,
                          float* __restrict__ xc,
                          __nv_bfloat16* __restrict__ xch, __nv_bfloat16* __restrict__ xcl,
                          int colOff, int CO)
{
    __shared__ int sidx[16][KNN];
    int ty = threadIdx.y, tx = threadIdx.x;
    int p = blockIdx.x * blockDim.y + ty;
    int b = p >> 10;
    for (int k = tx; k < KNN; k += blockDim.x) sidx[ty][k] = idx[p * KNN + k];
    __syncthreads();

    int st = 2 * CO;
    float4 tv = *reinterpret_cast<const float4*>(ut + (size_t)p * st + CO + tx * 4);
    float4 bv = *reinterpret_cast<const float4*>(tb + tx * 4);
    tv.x += bv.x; tv.y += bv.y; tv.z += bv.z; tv.w += bv.w;

    float4 mx = make_float4(NEG_INF, NEG_INF, NEG_INF, NEG_INF);
    #pragma unroll 4
    for (int k = 0; k < KNN; k++) {
        int j = sidx[ty][k];
        float4 v = *reinterpret_cast<const float4*>(
            ut + (size_t)((b << 10) + j) * st + tx * 4);
        mx.x = fmaxf(mx.x, v.x + tv.x);
        mx.y = fmaxf(mx.y, v.y + tv.y);
        mx.z = fmaxf(mx.z, v.z + tv.z);
        mx.w = fmaxf(mx.w, v.w + tv.w);
    }
    mx.x = (mx.x >= 0.f) ? mx.x : 0.01f * mx.x;
    mx.y = (mx.y >= 0.f) ? mx.y : 0.01f * mx.y;
    mx.z = (mx.z >= 0.f) ? mx.z : 0.01f * mx.z;
    mx.w = (mx.w >= 0.f) ? mx.w : 0.01f * mx.w;

    size_t o = (size_t)p * 512 + colOff + tx * 4;
    *reinterpret_cast<float4*>(xc + o) = mx;

    float vals[4] = {mx.x, mx.y, mx.z, mx.w};
    __nv_bfloat16 hb[4], lb[4];
    #pragma unroll
    for (int i = 0; i < 4; i++) {
        hb[i] = __float2bfloat16(vals[i]);
        lb[i] = __float2bfloat16(vals[i] - __bfloat162float(hb[i]));
    }
    *reinterpret_cast<uint2*>(xch + o) = *reinterpret_cast<uint2*>(hb);
    *reinterpret_cast<uint2*>(xcl + o) = *reinterpret_cast<uint2*>(lb);
}

// ---------------------------------------------------------------------------
__global__ void zero_pool(unsigned* pool)
{
    int i = blockIdx.x * 256 + threadIdx.x;
    if (i < B_ * 1024) pool[i] = 0u;
}

__device__ __forceinline__ float dec_pool(unsigned u)
{
    return (u & 0x80000000u) ? __uint_as_float(u & 0x7fffffffu) : __uint_as_float(~u);
}

// ---------------------------------------------------------------------------
__global__ void mlp1(const unsigned* __restrict__ pool, const float* __restrict__ w,
                     const float* __restrict__ g6, const float* __restrict__ b6,
                     float* __restrict__ y1)
{
    int b = blockIdx.y;
    int j = blockIdx.x * 4 + threadIdx.y;
    int lane = threadIdx.x;
    float s = 0.f;
    for (int c = lane; c < 1024; c += 32)
        s += dec_pool(pool[b * 1024 + c]) * w[j * 1024 + c];
    #pragma unroll
    for (int off = 16; off; off >>= 1) s += __shfl_xor_sync(0xffffffffu, s, off);
    if (lane == 0) {
        float v = s * (g6[j] * (1.0f / sqrtf(1.00001f))) + b6[j];
        y1[b * 512 + j] = (v >= 0.f) ? v : 0.01f * v;
    }
}

__global__ void mlp2(const float* __restrict__ y1, const float* __restrict__ w,
                     const float* __restrict__ wb, const float* __restrict__ g7,
                     const float* __restrict__ b7, float* __restrict__ y2)
{
    int b = blockIdx.y;
    int j = blockIdx.x * 4 + threadIdx.y;
    int lane = threadIdx.x;
    float s = 0.f;
    for (int c = lane; c < 512; c += 32) s += y1[b * 512 + c] * w[j * 512 + c];
    #pragma unroll
    for (int off = 16; off; off >>= 1) s += __shfl_xor_sync(0xffffffffu, s, off);
    if (lane == 0) {
        float v = (s + wb[j]) * (g7[j] * (1.0f / sqrtf(1.00001f))) + b7[j];
        y2[b * 256 + j] = (v >= 0.f) ? v : 0.01f * v;
    }
}

__global__ void mlp3(const float* __restrict__ y2, const float* __restrict__ w,
                     const float* __restrict__ wb, float* __restrict__ out)
{
    int b = blockIdx.y;
    int j = blockIdx.x * 4 + threadIdx.y;
    int lane = threadIdx.x;
    float s = 0.f;
    for (int c = lane; c < 256; c += 32) s += y2[b * 256 + c] * w[j * 256 + c];
    #pragma unroll
    for (int off = 16; off; off >>= 1) s += __shfl_xor_sync(0xffffffffu, s, off);
    if (lane == 0) out[b * 40 + j] = s + wb[j];
}

// ---------------------------------------------------------------------------
extern "C" void kernel_launch(void* const* d_in, const int* in_sizes, int n_in,
                              void* d_out, int out_size)
{
    const float* x        = (const float*)d_in[0];
    const float* conv1_w  = (const float*)d_in[1];
    const float* conv1_b  = (const float*)d_in[2];
    const float* bn1_g    = (const float*)d_in[3];
    const float* bn1_b    = (const float*)d_in[4];
    const float* conv2_w  = (const float*)d_in[5];
    const float* bn2_g    = (const float*)d_in[6];
    const float* bn2_b    = (const float*)d_in[7];
    const float* conv3_w  = (const float*)d_in[8];
    const float* bn3_g    = (const float*)d_in[9];
    const float* bn3_b    = (const float*)d_in[10];
    const float* conv4_w  = (const float*)d_in[11];
    const float* bn4_g    = (const float*)d_in[12];
    const float* bn4_b    = (const float*)d_in[13];
    const float* conv5_w  = (const float*)d_in[14];
    const float* lin1_w   = (const float*)d_in[15];
    const float* bn6_g    = (const float*)d_in[16];
    const float* bn6_b    = (const float*)d_in[17];
    const float* lin2_w   = (const float*)d_in[18];
    const float* lin2_b   = (const float*)d_in[19];
    const float* bn7_g    = (const float*)d_in[20];
    const float* bn7_b    = (const float*)d_in[21];
    const float* lin3_w   = (const float*)d_in[22];
    const float* lin3_b   = (const float*)d_in[23];

    float *xc, *inner, *ut, *utw, *tb, *xxp, *y1, *y2;
    __nv_bfloat16 *xch, *xcl, *utwh, *utwl, *c5h, *c5l;
    int* idx; unsigned* pool;
    cudaGetSymbolAddress((void**)&xc,    g_xc);
    cudaGetSymbolAddress((void**)&inner, g_inner);
    cudaGetSymbolAddress((void**)&xch,   g_xch);
    cudaGetSymbolAddress((void**)&xcl,   g_xcl);
    cudaGetSymbolAddress((void**)&ut,    g_ut);
    cudaGetSymbolAddress((void**)&utw,   g_utw);
    cudaGetSymbolAddress((void**)&utwh,  g_utwh);
    cudaGetSymbolAddress((void**)&utwl,  g_utwl);
    cudaGetSymbolAddress((void**)&c5h,   g_c5h);
    cudaGetSymbolAddress((void**)&c5l,   g_c5l);
    cudaGetSymbolAddress((void**)&tb,    g_tb);
    cudaGetSymbolAddress((void**)&xxp,   g_xx);
    cudaGetSymbolAddress((void**)&idx,   g_idx);
    cudaGetSymbolAddress((void**)&pool,  g_pool);
    cudaGetSymbolAddress((void**)&y1,    g_y1);
    cudaGetSymbolAddress((void**)&y2,    g_y2);

    cudaFuncSetAttribute(mma_gemm, cudaFuncAttributeMaxDynamicSharedMemorySize, MMA_SMEM);
    cudaFuncSetAttribute(mma_gemm_pool, cudaFuncAttributeMaxDynamicSharedMemorySize,
                         MMA_SMEM_POOL);

    // Second stream + fork/join events (host objects; created once, reused).
    static cudaStream_t s2 = nullptr;
    static cudaEvent_t evf[4], evj[4];
    if (s2 == nullptr) {
        cudaStreamCreateWithFlags(&s2, cudaStreamNonBlocking);
        for (int i = 0; i < 4; i++) {
            cudaEventCreateWithFlags(&evf[i], cudaEventDisableTiming);
            cudaEventCreateWithFlags(&evj[i], cudaEventDisableTiming);
        }
    }

    struct Layer {
        int inOff; int Cin; int Cout; int outOff;
        const float* W; const float* bias; const float* g; const float* bb;
    };
    Layer L[4] = {
        { -1,  3,   64,  0,   conv1_w, conv1_b, bn1_g, bn1_b },
        { 0,   64,  64,  64,  conv2_w, nullptr, bn2_g, bn2_b },
        { 64,  64,  128, 128, conv3_w, nullptr, bn3_g, bn3_b },
        { 128, 128, 256, 256, conv4_w, nullptr, bn4_g, bn4_b },
    };

    zero_pool<<<32, 256>>>(pool);

    for (int l = 0; l < 4; l++) {
        const Layer& a = L[l];
        const float* fin = (l == 0) ? x : (xc + a.inOff);
        int lda = (l == 0) ? 3 : 512;

        // fork: side stream computes [prep -> u|t GEMM] while main does
        // [gemm_sym -> diag -> topk]
        cudaEventRecord(evf[l], 0);
        cudaStreamWaitEvent(s2, evf[l], 0);

        if (l == 0)
            prep_c5<<<(1024 * 512 + 255) / 256, 256, 0, s2>>>(conv5_w, c5h, c5l);
        prep_w<<<(a.Cout * a.Cin + 255) / 256, 256, 0, s2>>>(
            a.W, a.Cin, a.Cout, a.bias, a.g, a.bb, utw, utwh, utwl, tb);
        if (l == 0) {
            gemm_f2<128, 64, 128><<<dim3(2, PTS / 128, 1), 128, 0, s2>>>(
                x, 3, 0, utw, 3, 0, ut, 128, 0, 3);
        } else {
            mma_gemm<<<dim3(2 * a.Cout / 128, PTS / 128, 1), 256, MMA_SMEM, s2>>>(
                xch + a.inOff, xcl + a.inOff, 512, 0,
                utwh, utwl, a.Cin, 0,
                ut, 2 * a.Cout, 0, a.Cin);
        }
        cudaEventRecord(evj[l], s2);

        // main stream: KNN chain
        gemm_sym<<<dim3(36, 1, B_), 256>>>(
            fin, lda, (long long)N_ * lda, inner, N_, (long long)N_ * N_, a.Cin);
        diag_xx<<<32, 256>>>(inner, xxp);
        topk_kernel<<<PTS / 8, 256>>>(inner, xxp, idx);

        // join, then gather
        cudaStreamWaitEvent(0, evj[l], 0);
        int cx = a.Cout / 4;
        int ppb = 1024 / a.Cout;
        if (ppb > 16) ppb = 16;
        gathermax<<<PTS / ppb, dim3(cx, ppb)>>>(ut, tb, idx, xc, xch, xcl,
                                                a.outOff, a.Cout);
    }

    // conv5 fused with global max-pool (e never materialized)
    mma_gemm_pool<<<dim3(8, PTS / 128, 1), 256, MMA_SMEM_POOL>>>(
        xch, xcl, 512, c5h, c5l, 512, pool, 512);

    mlp1<<<dim3(128, B_), dim3(32, 4)>>>(pool, lin1_w, bn6_g, bn6_b, y1);
    mlp2<<<dim3(64, B_),  dim3(32, 4)>>>(y1, lin2_w, lin2_b, bn7_g, bn7_b, y2);
    mlp3<<<dim3(10, B_),  dim3(32, 4)>>>(y2, lin3_w, lin3_b, (float*)d_out);
}